// round 2
// baseline (speedup 1.0000x reference)
#include <cuda_runtime.h>
#include <cstdint>

// LSTM: N=64, T=512, D=1024, H=1024, G=4096.
// Phase A: xW = x @ Wx + b  (32768x4096x1024 fp32 GEMM, FFMA2).
// Phase B: ONE persistent kernel, 128 CTAs (one per SM, co-resident), Wh slice
//          resident in SMEM for all 512 steps, grid-wide atomic barrier per step,
//          cell state in registers, h broadcast via cp.async double buffering.

#define N_  64
#define T_  512
#define D_  1024
#define H_  1024
#define G_  4096
#define M_  (N_ * T_)   // 32768
#define NCTA 128

typedef unsigned long long ull;

// Scratch: device globals (no runtime allocation allowed).
static __device__ __align__(16) float g_xw[(size_t)M_ * G_];   // 512 MB
static __device__ __align__(16) float g_h[2][N_ * H_];         // h ping-pong
static __device__ unsigned g_count;                            // grid barrier

// ---------- packed f32x2 helpers (FFMA2: 2x fp32 FMA throughput) ----------
__device__ __forceinline__ ull pack2(float x, float y) {
    ull r;
    asm("mov.b64 %0, {%1, %2};" : "=l"(r) : "f"(x), "f"(y));
    return r;
}
__device__ __forceinline__ void unpack2(ull v, float &x, float &y) {
    asm("mov.b64 {%0, %1}, %2;" : "=f"(x), "=f"(y) : "l"(v));
}
__device__ __forceinline__ void ffma2(ull &c, ull a, ull b) {
    asm("fma.rn.f32x2 %0, %1, %2, %0;" : "+l"(c) : "l"(a), "l"(b));
}

__device__ __forceinline__ float sigmoidf_(float x) {
    return 1.0f / (1.0f + __expf(-x));
}
__device__ __forceinline__ float fast_tanh(float x) {
    float ax = fabsf(x);
    float e = __expf(-2.0f * ax);            // in (0,1], no overflow
    float t = (1.0f - e) / (1.0f + e);
    return copysignf(t, x);
}

// ---------- cp.async helpers ----------
__device__ __forceinline__ void cp16(void* s, const void* g) {
    unsigned sa = (unsigned)__cvta_generic_to_shared(s);
    asm volatile("cp.async.ca.shared.global [%0], [%1], 16;" :: "r"(sa), "l"(g));
}
__device__ __forceinline__ void cp_commit() {
    asm volatile("cp.async.commit_group;");
}
__device__ __forceinline__ void cp_waitall() {
    asm volatile("cp.async.wait_group 0;");
}

// ---------------- init: h = h0, zero barrier ----------------
__global__ void init_kernel(const float* __restrict__ h0) {
    int i = blockIdx.x * blockDim.x + threadIdx.x;
    if (i < N_ * H_) g_h[0][i] = h0[i];
    if (i == 0) g_count = 0u;
}

// ---------------- Phase A: xW = x @ Wx + b ----------------
// 128x128x8 tile, 256 threads, 8x8 per-thread (as 8x4 f32x2), double-buffered smem.
__global__ __launch_bounds__(256, 2)
void gemm_xw_kernel(const float* __restrict__ X,
                    const float* __restrict__ Wx,
                    const float* __restrict__ bias) {
    __shared__ __align__(16) float As[2][8][132];
    __shared__ __align__(16) float Bs[2][8][128];

    const int tid = threadIdx.x;
    const int bx = blockIdx.x;
    const int by = blockIdx.y;
    const int tx = tid & 15;
    const int ty = tid >> 4;

    const int ar = tid >> 1;
    const int ak = (tid & 1) * 4;
    const float* aptr = X + (size_t)(by * 128 + ar) * D_ + ak;
    const int bk = tid >> 5;
    const int bc = (tid & 31) * 4;
    const float* bptr = Wx + (size_t)bk * G_ + bx * 128 + bc;

    ull acc[8][4];
    #pragma unroll
    for (int i = 0; i < 8; i++)
        #pragma unroll
        for (int j = 0; j < 4; j++) acc[i][j] = 0ULL;

    float4 ra = *(const float4*)(aptr);
    float4 rb = *(const float4*)(bptr);
    As[0][ak + 0][ar] = ra.x; As[0][ak + 1][ar] = ra.y;
    As[0][ak + 2][ar] = ra.z; As[0][ak + 3][ar] = ra.w;
    *(float4*)&Bs[0][bk][bc] = rb;
    __syncthreads();

    int buf = 0;
    const int NT = D_ / 8;
    for (int kt = 0; kt < NT; kt++) {
        if (kt + 1 < NT) {
            ra = *(const float4*)(aptr + (kt + 1) * 8);
            rb = *(const float4*)(bptr + (size_t)(kt + 1) * 8 * G_);
        }
        #pragma unroll
        for (int k = 0; k < 8; k++) {
            float4 a0 = *(const float4*)&As[buf][k][ty * 8];
            float4 a1 = *(const float4*)&As[buf][k][ty * 8 + 4];
            float4 b0 = *(const float4*)&Bs[buf][k][tx * 8];
            float4 b1 = *(const float4*)&Bs[buf][k][tx * 8 + 4];
            ull bp0 = pack2(b0.x, b0.y);
            ull bp1 = pack2(b0.z, b0.w);
            ull bp2 = pack2(b1.x, b1.y);
            ull bp3 = pack2(b1.z, b1.w);
            float av[8] = {a0.x, a0.y, a0.z, a0.w, a1.x, a1.y, a1.z, a1.w};
            #pragma unroll
            for (int i = 0; i < 8; i++) {
                ull ap = pack2(av[i], av[i]);
                ffma2(acc[i][0], ap, bp0);
                ffma2(acc[i][1], ap, bp1);
                ffma2(acc[i][2], ap, bp2);
                ffma2(acc[i][3], ap, bp3);
            }
        }
        if (kt + 1 < NT) {
            int nb = buf ^ 1;
            As[nb][ak + 0][ar] = ra.x; As[nb][ak + 1][ar] = ra.y;
            As[nb][ak + 2][ar] = ra.z; As[nb][ak + 3][ar] = ra.w;
            *(float4*)&Bs[nb][bk][bc] = rb;
            __syncthreads();
            buf = nb;
        }
    }

    const int colbase = bx * 128 + tx * 8;
    float4 bb0 = *(const float4*)(bias + colbase);
    float4 bb1 = *(const float4*)(bias + colbase + 4);
    #pragma unroll
    for (int i = 0; i < 8; i++) {
        int row = by * 128 + ty * 8 + i;
        float x0, x1, x2, x3, x4, x5, x6, x7;
        unpack2(acc[i][0], x0, x1); unpack2(acc[i][1], x2, x3);
        unpack2(acc[i][2], x4, x5); unpack2(acc[i][3], x6, x7);
        float4 o0 = {x0 + bb0.x, x1 + bb0.y, x2 + bb0.z, x3 + bb0.w};
        float4 o1 = {x4 + bb1.x, x5 + bb1.y, x6 + bb1.z, x7 + bb1.w};
        float* cp = g_xw + (size_t)row * G_ + colbase;
        *(float4*)cp = o0;
        *(float4*)(cp + 4) = o1;
    }
}

// ---------------- Phase B: persistent recurrent kernel ----------------
// CTA b owns h-columns [b*8, b*8+8) across all 4 gates (32 Wh columns).
// SMEM: Whs[1024][32] (128 KB, resident all steps) + h chunks (2x33 KB) + sm_a.
#define SMEM_WHS   0
#define SMEM_HS0   131072
#define SMEM_HS1   (131072 + 33792)
#define SMEM_SMA   (131072 + 67584)
#define SMEM_TOTAL (131072 + 67584 + 9216)   // 207872

__global__ __launch_bounds__(256, 1)
void lstm_persistent(const float* __restrict__ Wh,
                     float* __restrict__ out) {
    extern __shared__ char smem_raw[];
    float (*Whs)[32]  = (float(*)[32])(smem_raw + SMEM_WHS);
    float (*hsA)[132] = (float(*)[132])(smem_raw + SMEM_HS0);
    float (*hsB)[132] = (float(*)[132])(smem_raw + SMEM_HS1);
    float (*sm_a)[36] = (float(*)[36])(smem_raw + SMEM_SMA);

    const int tid = threadIdx.x;
    const int j0  = blockIdx.x * 8;

    // Load this CTA's Wh slice once: Whs[k][g*8+jj] = Wh[k][g*1024 + j0 + jj]
    for (int idx = tid; idx < 8192; idx += 256) {
        int k  = idx >> 3;
        int q4 = idx & 7;          // which float4 of the 32-col row
        int g  = q4 >> 1;          // gate
        int jj = (q4 & 1) * 4;
        float4 v = *(const float4*)(Wh + (size_t)k * G_ + g * H_ + j0 + jj);
        *(float4*)&Whs[k][q4 * 4] = v;
    }
    __syncthreads();

    // GEMM mapping: thread -> row m (0..63), gate c (0..3), cols jj 0..7
    const int m  = tid >> 2;
    const int c8 = (tid & 3) * 8;
    // epilogue mapping: elements e = tid and tid+256 of 512 (m,jj) pairs
    const int em1 = tid >> 3, ej = tid & 7;
    const int em2 = em1 + 32;
    float cc1 = 0.0f, cc2 = 0.0f;    // register-resident cell state
    // h chunk loader mapping
    const int lr = tid >> 5;          // base row
    const int lq = (tid & 31) * 4;    // float offset within 128-wide chunk

    for (int t = 0; t < T_; t++) {
        const float* hin  = g_h[t & 1];
        float*       hout = g_h[(t & 1) ^ 1];

        // prefetch xW gate pre-activations for epilogue (hidden behind GEMM)
        size_t xb1 = ((size_t)em1 * T_ + t) * G_ + j0 + ej;
        size_t xb2 = ((size_t)em2 * T_ + t) * G_ + j0 + ej;
        float xi1 = g_xw[xb1], xf1 = g_xw[xb1 + 1024], xo1 = g_xw[xb1 + 2048], xg1 = g_xw[xb1 + 3072];
        float xi2 = g_xw[xb2], xf2 = g_xw[xb2 + 1024], xo2 = g_xw[xb2 + 2048], xg2 = g_xw[xb2 + 3072];

        // stage h chunk 0
        #pragma unroll
        for (int i = 0; i < 8; i++)
            cp16(&hsA[lr + 8 * i][lq], hin + (size_t)(lr + 8 * i) * H_ + lq);
        cp_commit();
        cp_waitall();
        __syncthreads();

        ull acc0 = 0, acc1 = 0, acc2 = 0, acc3 = 0;
        float (*cur)[132] = hsA;
        float (*nxt)[132] = hsB;

        for (int ch = 0; ch < 8; ch++) {
            if (ch < 7) {
                int kb = (ch + 1) * 128;
                #pragma unroll
                for (int i = 0; i < 8; i++)
                    cp16(&nxt[lr + 8 * i][lq], hin + (size_t)(lr + 8 * i) * H_ + kb + lq);
                cp_commit();
            }
            const int kbase = ch * 128;
            const float* hrow = &cur[m][0];
            #pragma unroll 4
            for (int k4 = 0; k4 < 32; k4++) {
                float4 hv = *(const float4*)(hrow + k4 * 4);
                #pragma unroll
                for (int u = 0; u < 4; u++) {
                    const float* wp = &Whs[kbase + k4 * 4 + u][c8];
                    ulonglong2 bA = *(const ulonglong2*)wp;
                    ulonglong2 bB = *(const ulonglong2*)(wp + 4);
                    float hu = (&hv.x)[u];
                    ull hp = pack2(hu, hu);
                    ffma2(acc0, hp, bA.x);
                    ffma2(acc1, hp, bA.y);
                    ffma2(acc2, hp, bB.x);
                    ffma2(acc3, hp, bB.y);
                }
            }
            cp_waitall();
            __syncthreads();
            float (*tmp)[132] = cur; cur = nxt; nxt = tmp;
        }

        // scatter accumulators to smem for gate fusion
        {
            float v0, v1;
            unpack2(acc0, v0, v1); sm_a[m][c8 + 0] = v0; sm_a[m][c8 + 1] = v1;
            unpack2(acc1, v0, v1); sm_a[m][c8 + 2] = v0; sm_a[m][c8 + 3] = v1;
            unpack2(acc2, v0, v1); sm_a[m][c8 + 4] = v0; sm_a[m][c8 + 5] = v1;
            unpack2(acc3, v0, v1); sm_a[m][c8 + 6] = v0; sm_a[m][c8 + 7] = v1;
        }
        __syncthreads();

        // fused gates + state update (c in registers)
        {
            float ai = sm_a[em1][0  + ej] + xi1;
            float af = sm_a[em1][8  + ej] + xf1;
            float ao = sm_a[em1][16 + ej] + xo1;
            float ag = sm_a[em1][24 + ej] + xg1;
            float ig = sigmoidf_(ai), fg = sigmoidf_(af), og = sigmoidf_(ao);
            float gg = fast_tanh(ag);
            cc1 = fg * cc1 + ig * gg;
            float h = og * fast_tanh(cc1);
            hout[em1 * H_ + j0 + ej] = h;
            out[((size_t)em1 * T_ + t) * H_ + j0 + ej] = h;
        }
        {
            float ai = sm_a[em2][0  + ej] + xi2;
            float af = sm_a[em2][8  + ej] + xf2;
            float ao = sm_a[em2][16 + ej] + xo2;
            float ag = sm_a[em2][24 + ej] + xg2;
            float ig = sigmoidf_(ai), fg = sigmoidf_(af), og = sigmoidf_(ao);
            float gg = fast_tanh(ag);
            cc2 = fg * cc2 + ig * gg;
            float h = og * fast_tanh(cc2);
            hout[em2 * H_ + j0 + ej] = h;
            out[((size_t)em2 * T_ + t) * H_ + j0 + ej] = h;
        }

        // grid-wide barrier
        __threadfence();
        __syncthreads();
        if (tid == 0) {
            atomicAdd(&g_count, 1u);
            unsigned want = (unsigned)(t + 1) * NCTA;
            unsigned v;
            do {
                asm volatile("ld.acquire.gpu.global.u32 %0, [%1];"
                             : "=r"(v) : "l"(&g_count) : "memory");
            } while (v < want);
        }
        __syncthreads();
    }
}

// ---------------- launch ----------------
extern "C" void kernel_launch(void* const* d_in, const int* in_sizes, int n_in,
                              void* d_out, int out_size) {
    const float* x  = (const float*)d_in[0];   // (N, T, D)
    const float* h0 = (const float*)d_in[1];   // (N, H)
    const float* Wx = (const float*)d_in[2];   // (D, 4H)
    const float* Wh = (const float*)d_in[3];   // (H, 4H)
    const float* b  = (const float*)d_in[4];   // (4H,)
    float* out = (float*)d_out;                // (N, T, H)

    init_kernel<<<(N_ * H_ + 255) / 256, 256>>>(h0);

    dim3 gridA(G_ / 128, M_ / 128);
    gemm_xw_kernel<<<gridA, 256>>>(x, Wx, b);

    cudaFuncSetAttribute(lstm_persistent,
                         cudaFuncAttributeMaxDynamicSharedMemorySize, SMEM_TOTAL);
    lstm_persistent<<<NCTA, 256, SMEM_TOTAL>>>(Wh, out);
}

// round 3
// speedup vs baseline: 2.2793x; 2.2793x over previous
#include <cuda_runtime.h>
#include <cstdint>

// LSTM: N=64, T=512, D=1024, H=1024, G=4096.
// Phase A: xW = x @ Wx + b  (32768x4096x1024 fp32 GEMM, FFMA2).
// Phase B: ONE persistent kernel, 128 CTAs, Wh slice SMEM-resident across all
//          512 steps, h kept TRANSPOSED [j][m] in global, cp.async-streamed
//          [k][m] chunks, 2-way k-split GEMM, register cell state, grid barrier
//          with nanosleep backoff.

#define N_  64
#define T_  512
#define D_  1024
#define H_  1024
#define G_  4096
#define M_  (N_ * T_)   // 32768
#define NCTA 128

typedef unsigned long long ull;

// Scratch: device globals (no runtime allocation allowed).
static __device__ __align__(16) float g_xw[(size_t)M_ * G_];   // 512 MB
static __device__ __align__(16) float g_ht[2][H_ * N_];        // h transposed [j][m]
static __device__ unsigned g_count;                            // grid barrier

// ---------- packed f32x2 helpers ----------
__device__ __forceinline__ ull pack2(float x, float y) {
    ull r;
    asm("mov.b64 %0, {%1, %2};" : "=l"(r) : "f"(x), "f"(y));
    return r;
}
__device__ __forceinline__ void unpack2(ull v, float &x, float &y) {
    asm("mov.b64 {%0, %1}, %2;" : "=f"(x), "=f"(y) : "l"(v));
}
__device__ __forceinline__ void ffma2(ull &c, ull a, ull b) {
    asm("fma.rn.f32x2 %0, %1, %2, %0;" : "+l"(c) : "l"(a), "l"(b));
}

__device__ __forceinline__ float sigmoidf_(float x) {
    return 1.0f / (1.0f + __expf(-x));
}
__device__ __forceinline__ float fast_tanh(float x) {
    float ax = fabsf(x);
    float e = __expf(-2.0f * ax);
    float t = (1.0f - e) / (1.0f + e);
    return copysignf(t, x);
}

// ---------- cp.async helpers ----------
__device__ __forceinline__ void cp16(void* s, const void* g) {
    unsigned sa = (unsigned)__cvta_generic_to_shared(s);
    asm volatile("cp.async.ca.shared.global [%0], [%1], 16;" :: "r"(sa), "l"(g));
}
__device__ __forceinline__ void cp_commit() {
    asm volatile("cp.async.commit_group;");
}
__device__ __forceinline__ void cp_waitall() {
    asm volatile("cp.async.wait_group 0;");
}

// ---------------- init: h0 -> transposed, zero barrier ----------------
__global__ void init_kernel(const float* __restrict__ h0) {
    int i = blockIdx.x * blockDim.x + threadIdx.x;   // over N*H
    if (i < N_ * H_) {
        int m = i / H_, j = i % H_;
        g_ht[0][j * N_ + m] = h0[i];
    }
    if (i == 0) g_count = 0u;
}

// ---------------- Phase A: xW = x @ Wx + b (unchanged) ----------------
__global__ __launch_bounds__(256, 2)
void gemm_xw_kernel(const float* __restrict__ X,
                    const float* __restrict__ Wx,
                    const float* __restrict__ bias) {
    __shared__ __align__(16) float As[2][8][132];
    __shared__ __align__(16) float Bs[2][8][128];

    const int tid = threadIdx.x;
    const int bx = blockIdx.x;
    const int by = blockIdx.y;
    const int tx = tid & 15;
    const int ty = tid >> 4;

    const int ar = tid >> 1;
    const int ak = (tid & 1) * 4;
    const float* aptr = X + (size_t)(by * 128 + ar) * D_ + ak;
    const int bk = tid >> 5;
    const int bc = (tid & 31) * 4;
    const float* bptr = Wx + (size_t)bk * G_ + bx * 128 + bc;

    ull acc[8][4];
    #pragma unroll
    for (int i = 0; i < 8; i++)
        #pragma unroll
        for (int j = 0; j < 4; j++) acc[i][j] = 0ULL;

    float4 ra = *(const float4*)(aptr);
    float4 rb = *(const float4*)(bptr);
    As[0][ak + 0][ar] = ra.x; As[0][ak + 1][ar] = ra.y;
    As[0][ak + 2][ar] = ra.z; As[0][ak + 3][ar] = ra.w;
    *(float4*)&Bs[0][bk][bc] = rb;
    __syncthreads();

    int buf = 0;
    const int NT = D_ / 8;
    for (int kt = 0; kt < NT; kt++) {
        if (kt + 1 < NT) {
            ra = *(const float4*)(aptr + (kt + 1) * 8);
            rb = *(const float4*)(bptr + (size_t)(kt + 1) * 8 * G_);
        }
        #pragma unroll
        for (int k = 0; k < 8; k++) {
            float4 a0 = *(const float4*)&As[buf][k][ty * 8];
            float4 a1 = *(const float4*)&As[buf][k][ty * 8 + 4];
            float4 b0 = *(const float4*)&Bs[buf][k][tx * 8];
            float4 b1 = *(const float4*)&Bs[buf][k][tx * 8 + 4];
            ull bp0 = pack2(b0.x, b0.y);
            ull bp1 = pack2(b0.z, b0.w);
            ull bp2 = pack2(b1.x, b1.y);
            ull bp3 = pack2(b1.z, b1.w);
            float av[8] = {a0.x, a0.y, a0.z, a0.w, a1.x, a1.y, a1.z, a1.w};
            #pragma unroll
            for (int i = 0; i < 8; i++) {
                ull ap = pack2(av[i], av[i]);
                ffma2(acc[i][0], ap, bp0);
                ffma2(acc[i][1], ap, bp1);
                ffma2(acc[i][2], ap, bp2);
                ffma2(acc[i][3], ap, bp3);
            }
        }
        if (kt + 1 < NT) {
            int nb = buf ^ 1;
            As[nb][ak + 0][ar] = ra.x; As[nb][ak + 1][ar] = ra.y;
            As[nb][ak + 2][ar] = ra.z; As[nb][ak + 3][ar] = ra.w;
            *(float4*)&Bs[nb][bk][bc] = rb;
            __syncthreads();
            buf = nb;
        }
    }

    const int colbase = bx * 128 + tx * 8;
    float4 bb0 = *(const float4*)(bias + colbase);
    float4 bb1 = *(const float4*)(bias + colbase + 4);
    #pragma unroll
    for (int i = 0; i < 8; i++) {
        int row = by * 128 + ty * 8 + i;
        float x0, x1, x2, x3, x4, x5, x6, x7;
        unpack2(acc[i][0], x0, x1); unpack2(acc[i][1], x2, x3);
        unpack2(acc[i][2], x4, x5); unpack2(acc[i][3], x6, x7);
        float4 o0 = {x0 + bb0.x, x1 + bb0.y, x2 + bb0.z, x3 + bb0.w};
        float4 o1 = {x4 + bb1.x, x5 + bb1.y, x6 + bb1.z, x7 + bb1.w};
        float* cp = g_xw + (size_t)row * G_ + colbase;
        *(float4*)cp = o0;
        *(float4*)(cp + 4) = o1;
    }
}

// ---------------- Phase B: persistent recurrent kernel ----------------
// CTA b owns h-columns [b*8, b*8+8) across 4 gates (32 Wh columns).
// SMEM: Whs[1024][32] 128KB resident + hs[2][128][64] 64KB + sm_a0/1 ~17KB.
#define CHUNK_K 128
#define SMEM_WHS   0
#define SMEM_HS    131072
#define SMEM_A0    (131072 + 65536)
#define SMEM_A1    (SMEM_A0 + 64 * 34 * 4)
#define SMEM_TOTAL (SMEM_A1 + 64 * 34 * 4)   // 214016

__global__ __launch_bounds__(256, 1)
void lstm_persistent(const float* __restrict__ Wh,
                     float* __restrict__ out) {
    extern __shared__ char smem_raw[];
    float (*Whs)[32] = (float(*)[32])(smem_raw + SMEM_WHS);
    float* hs        = (float*)(smem_raw + SMEM_HS);       // [2][128*64]
    float (*sm_a0)[34] = (float(*)[34])(smem_raw + SMEM_A0);
    float (*sm_a1)[34] = (float(*)[34])(smem_raw + SMEM_A1);

    const int tid = threadIdx.x;
    const int j0  = blockIdx.x * 8;

    // Load CTA's Wh slice once: Whs[k][g*8+jj] = Wh[k][g*1024 + j0 + jj]
    for (int idx = tid; idx < 8192; idx += 256) {
        int k  = idx >> 3;
        int q4 = idx & 7;
        int g  = q4 >> 1;
        int jj = (q4 & 1) * 4;
        float4 v = *(const float4*)(Wh + (size_t)k * G_ + g * H_ + j0 + jj);
        *(float4*)&Whs[k][q4 * 4] = v;
    }

    // GEMM mapping: kg = k-split group, thread tile 2m x 8cols
    const int kg  = tid >> 7;              // 0/1
    const int t7  = tid & 127;
    const int m0  = (t7 >> 2) * 2;         // 0..62 even
    const int c8  = (t7 & 3) * 8;          // 0,8,16,24
    float (*my_a)[34] = kg ? sm_a1 : sm_a0;

    // epilogue mapping (fixed across steps; c lives in registers)
    const int em1 = tid >> 3, ej = tid & 7;
    const int em2 = em1 + 32;
    float cc1 = 0.0f, cc2 = 0.0f;

    __syncthreads();

    for (int t = 0; t < T_; t++) {
        const float* hin  = g_ht[t & 1];
        float*       hout = g_ht[(t & 1) ^ 1];

        // prefetch xW pre-activations (consumed in epilogue)
        size_t xb1 = ((size_t)em1 * T_ + t) * G_ + j0 + ej;
        size_t xb2 = ((size_t)em2 * T_ + t) * G_ + j0 + ej;
        float xi1 = g_xw[xb1], xf1 = g_xw[xb1 + 1024], xo1 = g_xw[xb1 + 2048], xg1 = g_xw[xb1 + 3072];
        float xi2 = g_xw[xb2], xf2 = g_xw[xb2 + 1024], xo2 = g_xw[xb2 + 2048], xg2 = g_xw[xb2 + 3072];

        // stage chunk 0: hs[buf][k][m], k rows of 64 floats (256B)
        #pragma unroll
        for (int i = 0; i < 8; i++) {
            int lin = tid + 256 * i;            // 0..2047
            int off = lin * 4;                  // float offset in 8192-float chunk
            cp16(hs + off, hin + off);
        }
        cp_commit();
        cp_waitall();
        __syncthreads();

        ull a00 = 0, a01 = 0, a02 = 0, a03 = 0;
        ull a10 = 0, a11 = 0, a12 = 0, a13 = 0;
        int buf = 0;

        for (int ch = 0; ch < 8; ch++) {
            if (ch < 7) {
                const float* src = hin + (ch + 1) * (CHUNK_K * 64);
                float* dst = hs + (buf ^ 1) * (CHUNK_K * 64);
                #pragma unroll
                for (int i = 0; i < 8; i++) {
                    int off = (tid + 256 * i) * 4;
                    cp16(dst + off, src + off);
                }
                cp_commit();
            }
            const float* hbase = hs + buf * (CHUNK_K * 64) + kg * (64 * 64) + m0;
            const int wrow = ch * CHUNK_K + kg * 64;
            #pragma unroll 4
            for (int k = 0; k < 64; k++) {
                float2 hv = *(const float2*)(hbase + k * 64);
                const float* wp = &Whs[wrow + k][c8];
                ulonglong2 w0 = *(const ulonglong2*)wp;
                ulonglong2 w1 = *(const ulonglong2*)(wp + 4);
                ull h0p = pack2(hv.x, hv.x);
                ull h1p = pack2(hv.y, hv.y);
                ffma2(a00, h0p, w0.x); ffma2(a01, h0p, w0.y);
                ffma2(a02, h0p, w1.x); ffma2(a03, h0p, w1.y);
                ffma2(a10, h1p, w0.x); ffma2(a11, h1p, w0.y);
                ffma2(a12, h1p, w1.x); ffma2(a13, h1p, w1.y);
            }
            if (ch < 7) {
                cp_waitall();
                __syncthreads();
                buf ^= 1;
            }
        }

        // scatter partials (k-group g -> sm_aG)
        {
            float v0, v1;
            unpack2(a00, v0, v1); my_a[m0][c8 + 0] = v0; my_a[m0][c8 + 1] = v1;
            unpack2(a01, v0, v1); my_a[m0][c8 + 2] = v0; my_a[m0][c8 + 3] = v1;
            unpack2(a02, v0, v1); my_a[m0][c8 + 4] = v0; my_a[m0][c8 + 5] = v1;
            unpack2(a03, v0, v1); my_a[m0][c8 + 6] = v0; my_a[m0][c8 + 7] = v1;
            unpack2(a10, v0, v1); my_a[m0+1][c8 + 0] = v0; my_a[m0+1][c8 + 1] = v1;
            unpack2(a11, v0, v1); my_a[m0+1][c8 + 2] = v0; my_a[m0+1][c8 + 3] = v1;
            unpack2(a12, v0, v1); my_a[m0+1][c8 + 4] = v0; my_a[m0+1][c8 + 5] = v1;
            unpack2(a13, v0, v1); my_a[m0+1][c8 + 6] = v0; my_a[m0+1][c8 + 7] = v1;
        }
        __syncthreads();

        // fused gates + state update (c in registers), h written transposed
        {
            float ai = sm_a0[em1][0  + ej] + sm_a1[em1][0  + ej] + xi1;
            float af = sm_a0[em1][8  + ej] + sm_a1[em1][8  + ej] + xf1;
            float ao = sm_a0[em1][16 + ej] + sm_a1[em1][16 + ej] + xo1;
            float ag = sm_a0[em1][24 + ej] + sm_a1[em1][24 + ej] + xg1;
            float ig = sigmoidf_(ai), fg = sigmoidf_(af), og = sigmoidf_(ao);
            float gg = fast_tanh(ag);
            cc1 = fg * cc1 + ig * gg;
            float h = og * fast_tanh(cc1);
            hout[(j0 + ej) * N_ + em1] = h;
            out[((size_t)em1 * T_ + t) * H_ + j0 + ej] = h;
        }
        {
            float ai = sm_a0[em2][0  + ej] + sm_a1[em2][0  + ej] + xi2;
            float af = sm_a0[em2][8  + ej] + sm_a1[em2][8  + ej] + xf2;
            float ao = sm_a0[em2][16 + ej] + sm_a1[em2][16 + ej] + xo2;
            float ag = sm_a0[em2][24 + ej] + sm_a1[em2][24 + ej] + xg2;
            float ig = sigmoidf_(ai), fg = sigmoidf_(af), og = sigmoidf_(ao);
            float gg = fast_tanh(ag);
            cc2 = fg * cc2 + ig * gg;
            float h = og * fast_tanh(cc2);
            hout[(j0 + ej) * N_ + em2] = h;
            out[((size_t)em2 * T_ + t) * H_ + j0 + ej] = h;
        }

        // grid barrier (release h writes, then count + backoff spin)
        __threadfence();
        __syncthreads();
        if (tid == 0) {
            atomicAdd(&g_count, 1u);
            unsigned want = (unsigned)(t + 1) * NCTA;
            unsigned v;
            asm volatile("ld.acquire.gpu.global.u32 %0, [%1];"
                         : "=r"(v) : "l"(&g_count) : "memory");
            while (v < want) {
                __nanosleep(64);
                asm volatile("ld.acquire.gpu.global.u32 %0, [%1];"
                             : "=r"(v) : "l"(&g_count) : "memory");
            }
        }
        __syncthreads();
    }
}

// ---------------- launch ----------------
extern "C" void kernel_launch(void* const* d_in, const int* in_sizes, int n_in,
                              void* d_out, int out_size) {
    const float* x  = (const float*)d_in[0];   // (N, T, D)
    const float* h0 = (const float*)d_in[1];   // (N, H)
    const float* Wx = (const float*)d_in[2];   // (D, 4H)
    const float* Wh = (const float*)d_in[3];   // (H, 4H)
    const float* b  = (const float*)d_in[4];   // (4H,)
    float* out = (float*)d_out;                // (N, T, H)

    init_kernel<<<(N_ * H_ + 255) / 256, 256>>>(h0);

    dim3 gridA(G_ / 128, M_ / 128);
    gemm_xw_kernel<<<gridA, 256>>>(x, Wx, b);

    cudaFuncSetAttribute(lstm_persistent,
                         cudaFuncAttributeMaxDynamicSharedMemorySize, SMEM_TOTAL);
    lstm_persistent<<<NCTA, 256, SMEM_TOTAL>>>(Wh, out);
}

// round 5
// speedup vs baseline: 3.9119x; 1.7162x over previous
#include <cuda_runtime.h>
#include <cuda_bf16.h>
#include <cstdint>

// LSTM N=64, T=512, D=1024, H=1024, G=4096.
// Phase A: xW = x @ Wx + b  (fp32 FFMA2 GEMM, proven).
// Phase B: persistent kernel, 128 CTAs, mma.sync bf16 m16n8k16 (HMMA) with
//          3-term hi/lo split for fp32-grade precision. Wh slice SMEM-resident,
//          h streamed bf16 [n][k], register cell state, grid barrier per step.

#define N_  64
#define T_  512
#define D_  1024
#define H_  1024
#define G_  4096
#define M_  (N_ * T_)
#define NCTA 128

typedef unsigned long long ull;

// -------- device globals --------
static __device__ __align__(16) float         g_xw[(size_t)M_ * G_];          // 512 MB
static __device__ __align__(16) __nv_bfloat16 g_whs[NCTA * 2 * 32 * 1024];    // 16 MB split Wh^T
static __device__ __align__(16) __nv_bfloat16 g_hb[2][2][N_][H_];             // [phase][term][n][k]
static __device__ unsigned g_count;

// -------- packed f32x2 (phase A) --------
__device__ __forceinline__ ull pack2(float x, float y) {
    ull r; asm("mov.b64 %0, {%1, %2};" : "=l"(r) : "f"(x), "f"(y)); return r;
}
__device__ __forceinline__ void unpack2(ull v, float &x, float &y) {
    asm("mov.b64 {%0, %1}, %2;" : "=f"(x), "=f"(y) : "l"(v));
}
__device__ __forceinline__ void ffma2(ull &c, ull a, ull b) {
    asm("fma.rn.f32x2 %0, %1, %2, %0;" : "+l"(c) : "l"(a), "l"(b));
}

__device__ __forceinline__ float sigmoidf_(float x) { return 1.0f / (1.0f + __expf(-x)); }
__device__ __forceinline__ float fast_tanh(float x) {
    float ax = fabsf(x);
    float e = __expf(-2.0f * ax);
    float t = (1.0f - e) / (1.0f + e);
    return copysignf(t, x);
}

// -------- async copy --------
__device__ __forceinline__ void cp16(uint32_t s, const void* g) {
    asm volatile("cp.async.cg.shared.global [%0], [%1], 16;" :: "r"(s), "l"(g));
}
__device__ __forceinline__ void cp_commit()  { asm volatile("cp.async.commit_group;"); }
template <int NN>
__device__ __forceinline__ void cp_wait() {
    asm volatile("cp.async.wait_group %0;" :: "n"(NN));
}

__device__ __forceinline__ uint32_t smem_u32(const void* p) {
    uint32_t a;
    asm("{ .reg .u64 t; cvta.to.shared.u64 t, %1; cvt.u32.u64 %0, t; }" : "=r"(a) : "l"(p));
    return a;
}

// -------- mma.sync helpers --------
__device__ __forceinline__ void ldm4(uint32_t addr, uint32_t* r) {
    asm volatile("ldmatrix.sync.aligned.m8n8.x4.shared.b16 {%0,%1,%2,%3}, [%4];"
                 : "=r"(r[0]), "=r"(r[1]), "=r"(r[2]), "=r"(r[3]) : "r"(addr));
}
__device__ __forceinline__ void mma16816(float* d, const uint32_t* a, const uint32_t* b) {
    asm volatile(
        "mma.sync.aligned.m16n8k16.row.col.f32.bf16.bf16.f32 "
        "{%0,%1,%2,%3}, {%4,%5,%6,%7}, {%8,%9}, {%0,%1,%2,%3};"
        : "+f"(d[0]), "+f"(d[1]), "+f"(d[2]), "+f"(d[3])
        : "r"(a[0]), "r"(a[1]), "r"(a[2]), "r"(a[3]), "r"(b[0]), "r"(b[1]));
}

// ---------------- prep: split Wh^T into per-CTA slices ----------------
// CTA b, row m = g*8 + j  (gate g, hidden col b*8+j), k 0..1023.
__global__ void prep_wh(const float* __restrict__ Wh) {
    int b = blockIdx.x;
    int tid = threadIdx.x;
    int m = tid & 31;
    int g = m >> 3, j = m & 7;
    int col = g * 1024 + b * 8 + j;
    __nv_bfloat16* dh = g_whs + ((size_t)(b * 2 + 0) * 32 + m) * 1024;
    __nv_bfloat16* dl = g_whs + ((size_t)(b * 2 + 1) * 32 + m) * 1024;
    for (int k = tid >> 5; k < 1024; k += 8) {
        float w = Wh[(size_t)k * G_ + col];
        __nv_bfloat16 hi = __float2bfloat16(w);
        __nv_bfloat16 lo = __float2bfloat16(w - __bfloat162float(hi));
        dh[k] = hi;
        dl[k] = lo;
    }
}

// ---------------- prep: h0 split ----------------
__global__ void prep_h0(const float* __restrict__ h0) {
    int i = blockIdx.x * blockDim.x + threadIdx.x;
    if (i < N_ * H_) {
        int n = i >> 10, k = i & 1023;
        float h = h0[i];
        __nv_bfloat16 hi = __float2bfloat16(h);
        __nv_bfloat16 lo = __float2bfloat16(h - __bfloat162float(hi));
        g_hb[0][0][n][k] = hi;
        g_hb[0][1][n][k] = lo;
    }
    if (i == 0) g_count = 0u;
}

// ---------------- Phase A: xW = x @ Wx + b (unchanged, proven) ----------------
__global__ __launch_bounds__(256, 2)
void gemm_xw_kernel(const float* __restrict__ X,
                    const float* __restrict__ Wx,
                    const float* __restrict__ bias) {
    __shared__ __align__(16) float As[2][8][132];
    __shared__ __align__(16) float Bs[2][8][128];

    const int tid = threadIdx.x;
    const int bx = blockIdx.x;
    const int by = blockIdx.y;
    const int tx = tid & 15;
    const int ty = tid >> 4;

    const int ar = tid >> 1;
    const int ak = (tid & 1) * 4;
    const float* aptr = X + (size_t)(by * 128 + ar) * D_ + ak;
    const int bk = tid >> 5;
    const int bc = (tid & 31) * 4;
    const float* bptr = Wx + (size_t)bk * G_ + bx * 128 + bc;

    ull acc[8][4];
    #pragma unroll
    for (int i = 0; i < 8; i++)
        #pragma unroll
        for (int j = 0; j < 4; j++) acc[i][j] = 0ULL;

    float4 ra = *(const float4*)(aptr);
    float4 rb = *(const float4*)(bptr);
    As[0][ak + 0][ar] = ra.x; As[0][ak + 1][ar] = ra.y;
    As[0][ak + 2][ar] = ra.z; As[0][ak + 3][ar] = ra.w;
    *(float4*)&Bs[0][bk][bc] = rb;
    __syncthreads();

    int buf = 0;
    const int NT = D_ / 8;
    for (int kt = 0; kt < NT; kt++) {
        if (kt + 1 < NT) {
            ra = *(const float4*)(aptr + (kt + 1) * 8);
            rb = *(const float4*)(bptr + (size_t)(kt + 1) * 8 * G_);
        }
        #pragma unroll
        for (int k = 0; k < 8; k++) {
            float4 a0 = *(const float4*)&As[buf][k][ty * 8];
            float4 a1 = *(const float4*)&As[buf][k][ty * 8 + 4];
            float4 b0 = *(const float4*)&Bs[buf][k][tx * 8];
            float4 b1 = *(const float4*)&Bs[buf][k][tx * 8 + 4];
            ull bp0 = pack2(b0.x, b0.y);
            ull bp1 = pack2(b0.z, b0.w);
            ull bp2 = pack2(b1.x, b1.y);
            ull bp3 = pack2(b1.z, b1.w);
            float av[8] = {a0.x, a0.y, a0.z, a0.w, a1.x, a1.y, a1.z, a1.w};
            #pragma unroll
            for (int i = 0; i < 8; i++) {
                ull ap = pack2(av[i], av[i]);
                ffma2(acc[i][0], ap, bp0);
                ffma2(acc[i][1], ap, bp1);
                ffma2(acc[i][2], ap, bp2);
                ffma2(acc[i][3], ap, bp3);
            }
        }
        if (kt + 1 < NT) {
            int nb = buf ^ 1;
            As[nb][ak + 0][ar] = ra.x; As[nb][ak + 1][ar] = ra.y;
            As[nb][ak + 2][ar] = ra.z; As[nb][ak + 3][ar] = ra.w;
            *(float4*)&Bs[nb][bk][bc] = rb;
            __syncthreads();
            buf = nb;
        }
    }

    const int colbase = bx * 128 + tx * 8;
    float4 bb0 = *(const float4*)(bias + colbase);
    float4 bb1 = *(const float4*)(bias + colbase + 4);
    #pragma unroll
    for (int i = 0; i < 8; i++) {
        int row = by * 128 + ty * 8 + i;
        float x0, x1, x2, x3, x4, x5, x6, x7;
        unpack2(acc[i][0], x0, x1); unpack2(acc[i][1], x2, x3);
        unpack2(acc[i][2], x4, x5); unpack2(acc[i][3], x6, x7);
        float4 o0 = {x0 + bb0.x, x1 + bb0.y, x2 + bb0.z, x3 + bb0.w};
        float4 o1 = {x4 + bb1.x, x5 + bb1.y, x6 + bb1.z, x7 + bb1.w};
        float* cp = g_xw + (size_t)row * G_ + colbase;
        *(float4*)cp = o0;
        *(float4*)(cp + 4) = o1;
    }
}

// ---------------- Phase B SMEM layout ----------------
// Whs: 64 rows (2 terms x 32 m) x 1024 bf16, pitch 2064 B  -> 132096 B
// hbuf: 2 buffers x (128 rows (2 terms x 64 n) x 128 k bf16, pitch 272 B) -> 69632 B
// sm_p: [2 ksplit][32 m][66 n] f32 -> 16896 B
#define WHS_PITCH 2064
#define HB_OFF    132096
#define HB_PITCH  272
#define HB_CHUNK  34816
#define SMP_OFF   (132096 + 69632)        // 201728
#define SMEM_TOT  (SMP_OFF + 16896)       // 218624

__global__ __launch_bounds__(256, 1)
void lstm_mma(float* __restrict__ out) {
    extern __shared__ char smem[];
    const uint32_t sb = smem_u32(smem);
    float* sm_p = (float*)(smem + SMP_OFF);

    const int tid  = threadIdx.x;
    const int wid  = tid >> 5;
    const int lane = tid & 31;
    const int b    = blockIdx.x;

    // ---- one-time: load Wh slice into padded SMEM (8192 16B pieces) ----
    {
        const char* src = (const char*)(g_whs + (size_t)b * 2 * 32 * 1024);
        for (int p = tid; p < 8192; p += 256) {
            int row = p >> 7;          // 0..63
            int seg = p & 127;         // 16B within 2048
            cp16(sb + row * WHS_PITCH + seg * 16, src + row * 2048 + seg * 16);
        }
        cp_commit();
        cp_wait<0>();
        __syncthreads();
    }

    // warp tiling: wk = k-split half, wm = M half (16), wn = N half (32)
    const int wk = wid >> 2;
    const int wm = (wid >> 1) & 1;
    const int wn = wid & 1;

    // ldmatrix lane offsets
    const uint32_t a_lane = (uint32_t)((lane & 15) * WHS_PITCH + (lane >> 4) * 16);
    const uint32_t aHiBase = sb + (wm * 16) * WHS_PITCH + a_lane;
    const uint32_t aLoBase = aHiBase + 32 * WHS_PITCH;

    const int b_n  = ((lane >> 4) & 1) * 8 + (lane & 7);
    const int b_kh = (lane >> 3) & 1;
    // b row index within buffer: term*64 + n ; two n-tile-pairs at wn*32 and wn*32+16
    const uint32_t bOffH0 = (uint32_t)((0 * 64 + wn * 32 + b_n)      * HB_PITCH + b_kh * 16);
    const uint32_t bOffH1 = (uint32_t)((0 * 64 + wn * 32 + 16 + b_n) * HB_PITCH + b_kh * 16);
    const uint32_t bOffL0 = (uint32_t)((1 * 64 + wn * 32 + b_n)      * HB_PITCH + b_kh * 16);
    const uint32_t bOffL1 = (uint32_t)((1 * 64 + wn * 32 + 16 + b_n) * HB_PITCH + b_kh * 16);

    // epilogue mapping
    const int ej = tid & 7;          // hidden col within slice
    const int en = tid >> 3;         // batch rows en, en+32
    float cs1 = 0.0f, cs2 = 0.0f;

    // partial-store mapping
    const int prow = lane >> 2;
    const int pcol = (lane & 3) * 2;

    for (int t = 0; t < T_; t++) {
        const int p = t & 1, q = p ^ 1;
        const char* hsrc = (const char*)&g_hb[p][0][0][0];   // [term][n][k] bf16

        // prefetch xW pre-activations
        float xw1[4], xw2[4];
        {
            const float* x1 = g_xw + ((size_t)en        * T_ + t) * G_ + b * 8 + ej;
            const float* x2 = g_xw + ((size_t)(en + 32) * T_ + t) * G_ + b * 8 + ej;
            #pragma unroll
            for (int g = 0; g < 4; g++) { xw1[g] = x1[g * 1024]; xw2[g] = x2[g * 1024]; }
        }

        // preload chunk 0
        {
            const uint32_t dst = sb + HB_OFF;
            for (int pc = tid; pc < 2048; pc += 256) {
                int row = pc >> 4;         // term*64+n, 0..127
                int seg = pc & 15;
                cp16(dst + row * HB_PITCH + seg * 16,
                     hsrc + (size_t)row * 2048 + seg * 16);
            }
            cp_commit();
        }

        float d0[4], d1[4], d2[4], d3[4];
        #pragma unroll
        for (int i = 0; i < 4; i++) { d0[i] = 0; d1[i] = 0; d2[i] = 0; d3[i] = 0; }

        int buf = 0;
        for (int ch = 0; ch < 8; ch++) {
            cp_wait<0>();
            __syncthreads();
            if (ch < 7) {
                const uint32_t dst = sb + HB_OFF + (buf ^ 1) * HB_CHUNK;
                const char* s = hsrc + (size_t)(ch + 1) * 256;   // k offset bytes
                for (int pc = tid; pc < 2048; pc += 256) {
                    int row = pc >> 4;
                    int seg = pc & 15;
                    cp16(dst + row * HB_PITCH + seg * 16,
                         s + (size_t)row * 2048 + seg * 16);
                }
                cp_commit();
            }

            const uint32_t hb = sb + HB_OFF + buf * HB_CHUNK;
            const uint32_t aK = (uint32_t)((ch * 128 + wk * 64) * 2);
            const uint32_t bH0 = hb + bOffH0, bH1 = hb + bOffH1;
            const uint32_t bL0 = hb + bOffL0, bL1 = hb + bOffL1;
            const uint32_t bK  = (uint32_t)(wk * 128);           // k_local byte offset

            #pragma unroll
            for (int ks = 0; ks < 4; ks++) {
                uint32_t ah[4], al[4], bh[8], bl[8];
                uint32_t ka = aK + ks * 32;
                uint32_t kb = bK + ks * 32;
                ldm4(aHiBase + ka, ah);
                ldm4(aLoBase + ka, al);
                ldm4(bH0 + kb, bh);
                ldm4(bH1 + kb, bh + 4);
                ldm4(bL0 + kb, bl);
                ldm4(bL1 + kb, bl + 4);
                mma16816(d0, ah, bh);     mma16816(d1, ah, bh + 2);
                mma16816(d2, ah, bh + 4); mma16816(d3, ah, bh + 6);
                mma16816(d0, ah, bl);     mma16816(d1, ah, bl + 2);
                mma16816(d2, ah, bl + 4); mma16816(d3, ah, bl + 6);
                mma16816(d0, al, bh);     mma16816(d1, al, bh + 2);
                mma16816(d2, al, bh + 4); mma16816(d3, al, bh + 6);
            }
            buf ^= 1;
        }

        // ---- store partials to SMEM ----
        __syncthreads();   // all ldmatrix reads done before reuse of sm space? (sm_p separate; sync for sm_p RW ordering)
        {
            float* base = sm_p + (wk * 32 + wm * 16 + prow) * 66 + wn * 32 + pcol;
            float* base8 = base + 8 * 66;
            *(float2*)(base)        = make_float2(d0[0], d0[1]);
            *(float2*)(base8)       = make_float2(d0[2], d0[3]);
            *(float2*)(base + 8)    = make_float2(d1[0], d1[1]);
            *(float2*)(base8 + 8)   = make_float2(d1[2], d1[3]);
            *(float2*)(base + 16)   = make_float2(d2[0], d2[1]);
            *(float2*)(base8 + 16)  = make_float2(d2[2], d2[3]);
            *(float2*)(base + 24)   = make_float2(d3[0], d3[1]);
            *(float2*)(base8 + 24)  = make_float2(d3[2], d3[3]);
        }
        __syncthreads();

        // ---- gates + state update ----
        #pragma unroll
        for (int half = 0; half < 2; half++) {
            int n = half ? (en + 32) : en;
            float* xw = half ? xw2 : xw1;
            float& cc = half ? cs2 : cs1;
            float a[4];
            #pragma unroll
            for (int g = 0; g < 4; g++) {
                int row = g * 8 + ej;
                a[g] = sm_p[row * 66 + n] + sm_p[(32 + row) * 66 + n] + xw[g];
            }
            float ig = sigmoidf_(a[0]), fg = sigmoidf_(a[1]), og = sigmoidf_(a[2]);
            float gg = fast_tanh(a[3]);
            cc = fg * cc + ig * gg;
            float h = og * fast_tanh(cc);
            out[((size_t)n * T_ + t) * H_ + b * 8 + ej] = h;
            __nv_bfloat16 hi = __float2bfloat16(h);
            __nv_bfloat16 lo = __float2bfloat16(h - __bfloat162float(hi));
            g_hb[q][0][n][b * 8 + ej] = hi;
            g_hb[q][1][n][b * 8 + ej] = lo;
        }

        // ---- grid barrier ----
        __threadfence();
        __syncthreads();
        if (tid == 0) {
            atomicAdd(&g_count, 1u);
            unsigned want = (unsigned)(t + 1) * NCTA;
            unsigned v;
            asm volatile("ld.acquire.gpu.global.u32 %0, [%1];" : "=r"(v) : "l"(&g_count) : "memory");
            while (v < want) {
                __nanosleep(64);
                asm volatile("ld.acquire.gpu.global.u32 %0, [%1];" : "=r"(v) : "l"(&g_count) : "memory");
            }
        }
        __syncthreads();
    }
}

// ---------------- launch ----------------
extern "C" void kernel_launch(void* const* d_in, const int* in_sizes, int n_in,
                              void* d_out, int out_size) {
    const float* x  = (const float*)d_in[0];   // (N, T, D)
    const float* h0 = (const float*)d_in[1];   // (N, H)
    const float* Wx = (const float*)d_in[2];   // (D, 4H)
    const float* Wh = (const float*)d_in[3];   // (H, 4H)
    const float* b  = (const float*)d_in[4];   // (4H,)
    float* out = (float*)d_out;                // (N, T, H)

    prep_h0<<<(N_ * H_ + 255) / 256, 256>>>(h0);
    prep_wh<<<NCTA, 256>>>(Wh);

    dim3 gridA(G_ / 128, M_ / 128);
    gemm_xw_kernel<<<gridA, 256>>>(x, Wx, b);

    cudaFuncSetAttribute(lstm_mma, cudaFuncAttributeMaxDynamicSharedMemorySize, SMEM_TOT);
    lstm_mma<<<NCTA, 256, SMEM_TOT>>>(out);
}

// round 6
// speedup vs baseline: 4.7677x; 1.2188x over previous
#include <cuda_runtime.h>
#include <cuda_bf16.h>
#include <cstdint>

// LSTM N=64, T=512, D=1024, H=1024, G=4096.
// Phase A: xW = x @ Wx + b  (fp32 FFMA2 GEMM, proven).
// Phase B: persistent kernel, 128 CTAs x 512 threads, HMMA bf16 3-term split.
//   h stored in PRE-FRAGMENTED global layout (one LDG.128 = one full B fragment,
//   hi+lo) -> no smem staging, no LDGSTS bottleneck. Wh slice SMEM-resident.

#define N_  64
#define T_  512
#define D_  1024
#define H_  1024
#define G_  4096
#define M_  (N_ * T_)
#define NCTA 128

typedef unsigned long long ull;

// -------- device globals --------
static __device__ __align__(16) float         g_xw[(size_t)M_ * G_];        // 512 MB
static __device__ __align__(16) __nv_bfloat16 g_whs[NCTA * 2 * 32 * 1024];  // 16 MB split Wh^T
// h fragment layout: [phase][k16 0..63][n8 0..7][lane 0..31][8 bf16: hi b0,b1 | lo b0,b1]
static __device__ __align__(16) __nv_bfloat16 g_hf[2][64][8][32][8];
static __device__ unsigned g_count;

// -------- packed f32x2 (phase A) --------
__device__ __forceinline__ ull pack2(float x, float y) {
    ull r; asm("mov.b64 %0, {%1, %2};" : "=l"(r) : "f"(x), "f"(y)); return r;
}
__device__ __forceinline__ void unpack2(ull v, float &x, float &y) {
    asm("mov.b64 {%0, %1}, %2;" : "=f"(x), "=f"(y) : "l"(v));
}
__device__ __forceinline__ void ffma2(ull &c, ull a, ull b) {
    asm("fma.rn.f32x2 %0, %1, %2, %0;" : "+l"(c) : "l"(a), "l"(b));
}

__device__ __forceinline__ float sigmoidf_(float x) { return 1.0f / (1.0f + __expf(-x)); }
__device__ __forceinline__ float fast_tanh(float x) {
    float ax = fabsf(x);
    float e = __expf(-2.0f * ax);
    float t = (1.0f - e) / (1.0f + e);
    return copysignf(t, x);
}

// -------- async copy (Wh one-time load only) --------
__device__ __forceinline__ void cp16(uint32_t s, const void* g) {
    asm volatile("cp.async.cg.shared.global [%0], [%1], 16;" :: "r"(s), "l"(g));
}
__device__ __forceinline__ void cp_commit()  { asm volatile("cp.async.commit_group;"); }
__device__ __forceinline__ void cp_wait0()   { asm volatile("cp.async.wait_group 0;"); }

__device__ __forceinline__ uint32_t smem_u32(const void* p) {
    uint32_t a;
    asm("{ .reg .u64 t; cvta.to.shared.u64 t, %1; cvt.u32.u64 %0, t; }" : "=r"(a) : "l"(p));
    return a;
}

// -------- mma helpers --------
__device__ __forceinline__ void ldm4(uint32_t addr, uint32_t* r) {
    asm volatile("ldmatrix.sync.aligned.m8n8.x4.shared.b16 {%0,%1,%2,%3}, [%4];"
                 : "=r"(r[0]), "=r"(r[1]), "=r"(r[2]), "=r"(r[3]) : "r"(addr));
}
__device__ __forceinline__ void mma16816(float* d, const uint32_t* a, uint32_t b0, uint32_t b1) {
    asm volatile(
        "mma.sync.aligned.m16n8k16.row.col.f32.bf16.bf16.f32 "
        "{%0,%1,%2,%3}, {%4,%5,%6,%7}, {%8,%9}, {%0,%1,%2,%3};"
        : "+f"(d[0]), "+f"(d[1]), "+f"(d[2]), "+f"(d[3])
        : "r"(a[0]), "r"(a[1]), "r"(a[2]), "r"(a[3]), "r"(b0), "r"(b1));
}

// ---------------- prep: split Wh^T into per-CTA slices ----------------
__global__ void prep_wh(const float* __restrict__ Wh) {
    int b = blockIdx.x;
    int tid = threadIdx.x;
    int m = tid & 31;
    int g = m >> 3, j = m & 7;
    int col = g * 1024 + b * 8 + j;
    __nv_bfloat16* dh = g_whs + ((size_t)(b * 2 + 0) * 32 + m) * 1024;
    __nv_bfloat16* dl = g_whs + ((size_t)(b * 2 + 1) * 32 + m) * 1024;
    for (int k = tid >> 5; k < 1024; k += 8) {
        float w = Wh[(size_t)k * G_ + col];
        __nv_bfloat16 hi = __float2bfloat16(w);
        __nv_bfloat16 lo = __float2bfloat16(w - __bfloat162float(hi));
        dh[k] = hi;
        dl[k] = lo;
    }
}

// ---------------- prep: h0 -> fragment layout ----------------
__global__ void prep_h0(const float* __restrict__ h0) {
    int i = blockIdx.x * blockDim.x + threadIdx.x;
    if (i < N_ * H_) {
        int n = i >> 10, k = i & 1023;
        float h = h0[i];
        __nv_bfloat16 hi = __float2bfloat16(h);
        __nv_bfloat16 lo = __float2bfloat16(h - __bfloat162float(hi));
        int lane = (n & 7) * 4 + ((k & 7) >> 1);
        int el   = (((k >> 3) & 1) << 1) | (k & 1);
        g_hf[0][k >> 4][n >> 3][lane][el]     = hi;
        g_hf[0][k >> 4][n >> 3][lane][el + 4] = lo;
    }
    if (i == 0) g_count = 0u;
}

// ---------------- Phase A: xW = x @ Wx + b (unchanged, proven) ----------------
__global__ __launch_bounds__(256, 2)
void gemm_xw_kernel(const float* __restrict__ X,
                    const float* __restrict__ Wx,
                    const float* __restrict__ bias) {
    __shared__ __align__(16) float As[2][8][132];
    __shared__ __align__(16) float Bs[2][8][128];

    const int tid = threadIdx.x;
    const int bx = blockIdx.x;
    const int by = blockIdx.y;
    const int tx = tid & 15;
    const int ty = tid >> 4;

    const int ar = tid >> 1;
    const int ak = (tid & 1) * 4;
    const float* aptr = X + (size_t)(by * 128 + ar) * D_ + ak;
    const int bk = tid >> 5;
    const int bc = (tid & 31) * 4;
    const float* bptr = Wx + (size_t)bk * G_ + bx * 128 + bc;

    ull acc[8][4];
    #pragma unroll
    for (int i = 0; i < 8; i++)
        #pragma unroll
        for (int j = 0; j < 4; j++) acc[i][j] = 0ULL;

    float4 ra = *(const float4*)(aptr);
    float4 rb = *(const float4*)(bptr);
    As[0][ak + 0][ar] = ra.x; As[0][ak + 1][ar] = ra.y;
    As[0][ak + 2][ar] = ra.z; As[0][ak + 3][ar] = ra.w;
    *(float4*)&Bs[0][bk][bc] = rb;
    __syncthreads();

    int buf = 0;
    const int NT = D_ / 8;
    for (int kt = 0; kt < NT; kt++) {
        if (kt + 1 < NT) {
            ra = *(const float4*)(aptr + (kt + 1) * 8);
            rb = *(const float4*)(bptr + (size_t)(kt + 1) * 8 * G_);
        }
        #pragma unroll
        for (int k = 0; k < 8; k++) {
            float4 a0 = *(const float4*)&As[buf][k][ty * 8];
            float4 a1 = *(const float4*)&As[buf][k][ty * 8 + 4];
            float4 b0 = *(const float4*)&Bs[buf][k][tx * 8];
            float4 b1 = *(const float4*)&Bs[buf][k][tx * 8 + 4];
            ull bp0 = pack2(b0.x, b0.y);
            ull bp1 = pack2(b0.z, b0.w);
            ull bp2 = pack2(b1.x, b1.y);
            ull bp3 = pack2(b1.z, b1.w);
            float av[8] = {a0.x, a0.y, a0.z, a0.w, a1.x, a1.y, a1.z, a1.w};
            #pragma unroll
            for (int i = 0; i < 8; i++) {
                ull ap = pack2(av[i], av[i]);
                ffma2(acc[i][0], ap, bp0);
                ffma2(acc[i][1], ap, bp1);
                ffma2(acc[i][2], ap, bp2);
                ffma2(acc[i][3], ap, bp3);
            }
        }
        if (kt + 1 < NT) {
            int nb = buf ^ 1;
            As[nb][ak + 0][ar] = ra.x; As[nb][ak + 1][ar] = ra.y;
            As[nb][ak + 2][ar] = ra.z; As[nb][ak + 3][ar] = ra.w;
            *(float4*)&Bs[nb][bk][bc] = rb;
            __syncthreads();
            buf = nb;
        }
    }

    const int colbase = bx * 128 + tx * 8;
    float4 bb0 = *(const float4*)(bias + colbase);
    float4 bb1 = *(const float4*)(bias + colbase + 4);
    #pragma unroll
    for (int i = 0; i < 8; i++) {
        int row = by * 128 + ty * 8 + i;
        float x0, x1, x2, x3, x4, x5, x6, x7;
        unpack2(acc[i][0], x0, x1); unpack2(acc[i][1], x2, x3);
        unpack2(acc[i][2], x4, x5); unpack2(acc[i][3], x6, x7);
        float4 o0 = {x0 + bb0.x, x1 + bb0.y, x2 + bb0.z, x3 + bb0.w};
        float4 o1 = {x4 + bb1.x, x5 + bb1.y, x6 + bb1.z, x7 + bb1.w};
        float* cp = g_xw + (size_t)row * G_ + colbase;
        *(float4*)cp = o0;
        *(float4*)(cp + 4) = o1;
    }
}

// ---------------- Phase B SMEM ----------------
// Whs: 64 rows (2 terms x 32 m) x 1024 bf16, pitch 2064 B -> 132096 B
// sm_p: [4 ksplit][32 m][66 n] f32 -> 33792 B
#define WHS_PITCH 2064
#define SMP_OFF   132096
#define SMEM_TOT  (132096 + 33792)   // 165888

__global__ __launch_bounds__(512, 1)
void lstm_mma(float* __restrict__ out) {
    extern __shared__ char smem[];
    const uint32_t sb = smem_u32(smem);
    float* sm_p = (float*)(smem + SMP_OFF);   // [4][32][66]

    const int tid  = threadIdx.x;
    const int wid  = tid >> 5;
    const int lane = tid & 31;
    const int b    = blockIdx.x;

    // ---- one-time: Wh slice -> padded SMEM (8192 x 16B) ----
    {
        const char* src = (const char*)(g_whs + (size_t)b * 2 * 32 * 1024);
        for (int p = tid; p < 8192; p += 512) {
            int row = p >> 7;
            int seg = p & 127;
            cp16(sb + row * WHS_PITCH + seg * 16, src + row * 2048 + seg * 16);
        }
        cp_commit();
        cp_wait0();
        __syncthreads();
    }

    // warp tiling: wk (k 4-split, 256k each) x wm (m16 half) x wn (n32 half)
    const int wk = wid & 3;
    const int wm = (wid >> 2) & 1;
    const int wn = wid >> 3;
    const int kk0 = wk * 16;           // first k16 index of this warp

    // A ldmatrix lane address (hi term; lo = +32 rows)
    const uint32_t aHiBase = sb + (uint32_t)(wm * 16 + (lane & 15)) * WHS_PITCH
                                + (uint32_t)(lane >> 4) * 16;
    const uint32_t aLoBase = aHiBase + 32 * WHS_PITCH;

    // partial-store mapping
    const int prow = lane >> 2;
    const int pcol = (lane & 3) * 2;
    float* pbase  = sm_p + ((wk * 32) + wm * 16 + prow) * 66 + wn * 32 + pcol;

    // epilogue mapping: one (n, j) per thread
    const int en = tid >> 3;
    const int ej = tid & 7;
    const int jg = b * 8 + ej;         // global hidden col (= k of next step)
    float cc = 0.0f;
    // h fragment writer address components
    const int wlane = (en & 7) * 4 + ((jg & 7) >> 1);
    const int wel   = (((jg >> 3) & 1) << 1) | (jg & 1);

    for (int t = 0; t < T_; t++) {
        const int p = t & 1, q = p ^ 1;
        const __nv_bfloat16* hf = &g_hf[p][0][0][0][0];
        const uint4* bBase = (const uint4*)(hf) + (size_t)(wn * 4) * 32 + lane;
        // (uint4 index: kk*256 + nn*32 + lane)

        // prefetch xW pre-activations
        float xw[4];
        {
            const float* xp = g_xw + ((size_t)en * T_ + t) * G_ + jg;
            #pragma unroll
            for (int g = 0; g < 4; g++) xw[g] = xp[g * 1024];
        }

        float d[4][4];
        #pragma unroll
        for (int j = 0; j < 4; j++)
            #pragma unroll
            for (int i = 0; i < 4; i++) d[j][i] = 0.0f;

        uint4 bA[4], bB[4];
        uint32_t aA[8], aB[8];

        // preload s=0
        #pragma unroll
        for (int j = 0; j < 4; j++) bA[j] = bBase[(size_t)kk0 * 256 + j * 32];
        ldm4(aHiBase + kk0 * 32, aA);
        ldm4(aLoBase + kk0 * 32, aA + 4);

        #pragma unroll
        for (int s = 0; s < 16; s += 2) {
            // prefetch s+1
            {
                int kk = kk0 + s + 1;
                #pragma unroll
                for (int j = 0; j < 4; j++) bB[j] = bBase[(size_t)kk * 256 + j * 32];
                ldm4(aHiBase + kk * 32, aB);
                ldm4(aLoBase + kk * 32, aB + 4);
            }
            // compute s (term-outer to avoid accumulator RAW adjacency)
            #pragma unroll
            for (int j = 0; j < 4; j++) mma16816(d[j], aA,     bA[j].x, bA[j].y);
            #pragma unroll
            for (int j = 0; j < 4; j++) mma16816(d[j], aA,     bA[j].z, bA[j].w);
            #pragma unroll
            for (int j = 0; j < 4; j++) mma16816(d[j], aA + 4, bA[j].x, bA[j].y);
            // prefetch s+2
            if (s + 2 < 16) {
                int kk = kk0 + s + 2;
                #pragma unroll
                for (int j = 0; j < 4; j++) bA[j] = bBase[(size_t)kk * 256 + j * 32];
                ldm4(aHiBase + kk * 32, aA);
                ldm4(aLoBase + kk * 32, aA + 4);
            }
            // compute s+1
            #pragma unroll
            for (int j = 0; j < 4; j++) mma16816(d[j], aB,     bB[j].x, bB[j].y);
            #pragma unroll
            for (int j = 0; j < 4; j++) mma16816(d[j], aB,     bB[j].z, bB[j].w);
            #pragma unroll
            for (int j = 0; j < 4; j++) mma16816(d[j], aB + 4, bB[j].x, bB[j].y);
        }

        // ---- store partials ----
        #pragma unroll
        for (int j = 0; j < 4; j++) {
            *(float2*)(pbase + j * 8)          = make_float2(d[j][0], d[j][1]);
            *(float2*)(pbase + j * 8 + 8 * 66) = make_float2(d[j][2], d[j][3]);
        }
        __syncthreads();

        // ---- gates + state update ----
        {
            float a[4];
            #pragma unroll
            for (int g = 0; g < 4; g++) {
                int row = g * 8 + ej;
                float s0 = sm_p[(0 * 32 + row) * 66 + en] + sm_p[(1 * 32 + row) * 66 + en];
                float s1 = sm_p[(2 * 32 + row) * 66 + en] + sm_p[(3 * 32 + row) * 66 + en];
                a[g] = s0 + s1 + xw[g];
            }
            float ig = sigmoidf_(a[0]), fg = sigmoidf_(a[1]), og = sigmoidf_(a[2]);
            float gg = fast_tanh(a[3]);
            cc = fg * cc + ig * gg;
            float h = og * fast_tanh(cc);
            out[((size_t)en * T_ + t) * H_ + jg] = h;
            __nv_bfloat16 hi = __float2bfloat16(h);
            __nv_bfloat16 lo = __float2bfloat16(h - __bfloat162float(hi));
            g_hf[q][jg >> 4][en >> 3][wlane][wel]     = hi;
            g_hf[q][jg >> 4][en >> 3][wlane][wel + 4] = lo;
        }

        // ---- grid barrier ----
        __threadfence();
        __syncthreads();
        if (tid == 0) {
            atomicAdd(&g_count, 1u);
            unsigned want = (unsigned)(t + 1) * NCTA;
            unsigned v;
            asm volatile("ld.acquire.gpu.global.u32 %0, [%1];" : "=r"(v) : "l"(&g_count) : "memory");
            while (v < want) {
                __nanosleep(64);
                asm volatile("ld.acquire.gpu.global.u32 %0, [%1];" : "=r"(v) : "l"(&g_count) : "memory");
            }
        }
        __syncthreads();
    }
}

// ---------------- launch ----------------
extern "C" void kernel_launch(void* const* d_in, const int* in_sizes, int n_in,
                              void* d_out, int out_size) {
    const float* x  = (const float*)d_in[0];   // (N, T, D)
    const float* h0 = (const float*)d_in[1];   // (N, H)
    const float* Wx = (const float*)d_in[2];   // (D, 4H)
    const float* Wh = (const float*)d_in[3];   // (H, 4H)
    const float* b  = (const float*)d_in[4];   // (4H,)
    float* out = (float*)d_out;                // (N, T, H)

    prep_h0<<<(N_ * H_ + 255) / 256, 256>>>(h0);
    prep_wh<<<NCTA, 256>>>(Wh);

    dim3 gridA(G_ / 128, M_ / 128);
    gemm_xw_kernel<<<gridA, 256>>>(x, Wx, b);

    cudaFuncSetAttribute(lstm_mma, cudaFuncAttributeMaxDynamicSharedMemorySize, SMEM_TOT);
    lstm_mma<<<NCTA, 512, SMEM_TOT>>>(out);
}

// round 7
// speedup vs baseline: 5.2828x; 1.1080x over previous
#include <cuda_runtime.h>
#include <cuda_fp16.h>
#include <cstdint>

// LSTM N=64, T=512, D=1024, H=1024, G=4096.
// Phase A: xW = x @ Wx + b  (fp32 FFMA2 GEMM, near fp32 peak - unchanged).
// Phase B: persistent kernel, 128 CTAs x 512 threads, HMMA fp16 2-term split:
//   W = Whi + Wlo/2048 (exact fp16 pair, Wlo pre-scaled x2048, separate fp32
//   accumulator), h quantized to single fp16 per step (error ~2^-12, random).
//   h stored PRE-FRAGMENTED (LDG.128 = two B fragments). Wh SMEM-resident.

#define N_  64
#define T_  512
#define D_  1024
#define H_  1024
#define G_  4096
#define M_  (N_ * T_)
#define NCTA 128
#define INV2048 (1.0f / 2048.0f)

typedef unsigned long long ull;

// -------- device globals --------
static __device__ __align__(16) float  g_xw[(size_t)M_ * G_];        // 512 MB
static __device__ __align__(16) __half g_whs[NCTA * 2 * 32 * 1024];  // 16 MB split Wh^T (hi rows 0-31, lo*2048 rows 32-63 per CTA)
// h fragments: [phase][k16 0..63][np 0..3][lane 0..31][8 fp16]
//   fp16 idx = ((n>>3)&1)*4 + (((k>>3)&1)*2 + (k&1)); lane = (n&7)*4+((k&7)>>1)
static __device__ __align__(16) __half g_hf[2][64][4][32][8];
static __device__ unsigned g_count;

// -------- packed f32x2 (phase A) --------
__device__ __forceinline__ ull pack2(float x, float y) {
    ull r; asm("mov.b64 %0, {%1, %2};" : "=l"(r) : "f"(x), "f"(y)); return r;
}
__device__ __forceinline__ void unpack2(ull v, float &x, float &y) {
    asm("mov.b64 {%0, %1}, %2;" : "=f"(x), "=f"(y) : "l"(v));
}
__device__ __forceinline__ void ffma2(ull &c, ull a, ull b) {
    asm("fma.rn.f32x2 %0, %1, %2, %0;" : "+l"(c) : "l"(a), "l"(b));
}

__device__ __forceinline__ float sigmoidf_(float x) { return 1.0f / (1.0f + __expf(-x)); }
__device__ __forceinline__ float fast_tanh(float x) {
    float ax = fabsf(x);
    float e = __expf(-2.0f * ax);
    float t = (1.0f - e) / (1.0f + e);
    return copysignf(t, x);
}

// -------- async copy (Wh one-time load only) --------
__device__ __forceinline__ void cp16(uint32_t s, const void* g) {
    asm volatile("cp.async.cg.shared.global [%0], [%1], 16;" :: "r"(s), "l"(g));
}
__device__ __forceinline__ void cp_commit()  { asm volatile("cp.async.commit_group;"); }
__device__ __forceinline__ void cp_wait0()   { asm volatile("cp.async.wait_group 0;"); }

__device__ __forceinline__ uint32_t smem_u32(const void* p) {
    uint32_t a;
    asm("{ .reg .u64 t; cvta.to.shared.u64 t, %1; cvt.u32.u64 %0, t; }" : "=r"(a) : "l"(p));
    return a;
}

// -------- mma helpers --------
__device__ __forceinline__ void ldm4(uint32_t addr, uint32_t* r) {
    asm volatile("ldmatrix.sync.aligned.m8n8.x4.shared.b16 {%0,%1,%2,%3}, [%4];"
                 : "=r"(r[0]), "=r"(r[1]), "=r"(r[2]), "=r"(r[3]) : "r"(addr));
}
__device__ __forceinline__ void mma16816(float* d, const uint32_t* a, uint32_t b0, uint32_t b1) {
    asm volatile(
        "mma.sync.aligned.m16n8k16.row.col.f32.f16.f16.f32 "
        "{%0,%1,%2,%3}, {%4,%5,%6,%7}, {%8,%9}, {%0,%1,%2,%3};"
        : "+f"(d[0]), "+f"(d[1]), "+f"(d[2]), "+f"(d[3])
        : "r"(a[0]), "r"(a[1]), "r"(a[2]), "r"(a[3]), "r"(b0), "r"(b1));
}

// ---------------- prep: split Wh^T into per-CTA slices (fp16 hi + lo*2048) ----
__global__ void prep_wh(const float* __restrict__ Wh) {
    int b = blockIdx.x;
    int tid = threadIdx.x;
    int m = tid & 31;
    int g = m >> 3, j = m & 7;
    int col = g * 1024 + b * 8 + j;
    __half* dh = g_whs + ((size_t)(b * 2 + 0) * 32 + m) * 1024;
    __half* dl = g_whs + ((size_t)(b * 2 + 1) * 32 + m) * 1024;
    for (int k = tid >> 5; k < 1024; k += 8) {
        float w = Wh[(size_t)k * G_ + col];
        __half hi = __float2half_rn(w);
        __half lo = __float2half_rn((w - __half2float(hi)) * 2048.0f);
        dh[k] = hi;
        dl[k] = lo;
    }
}

// ---------------- prep: h0 -> fp16 fragment layout ----------------
__global__ void prep_h0(const float* __restrict__ h0) {
    int i = blockIdx.x * blockDim.x + threadIdx.x;
    if (i < N_ * H_) {
        int n = i >> 10, k = i & 1023;
        int lane = (n & 7) * 4 + ((k & 7) >> 1);
        int idx8 = ((n >> 3) & 1) * 4 + (((k >> 3) & 1) * 2 + (k & 1));
        g_hf[0][k >> 4][n >> 4][lane][idx8] = __float2half_rn(h0[i]);
    }
    if (i == 0) g_count = 0u;
}

// ---------------- Phase A: xW = x @ Wx + b (unchanged, proven) ----------------
__global__ __launch_bounds__(256, 2)
void gemm_xw_kernel(const float* __restrict__ X,
                    const float* __restrict__ Wx,
                    const float* __restrict__ bias) {
    __shared__ __align__(16) float As[2][8][132];
    __shared__ __align__(16) float Bs[2][8][128];

    const int tid = threadIdx.x;
    const int bx = blockIdx.x;
    const int by = blockIdx.y;
    const int tx = tid & 15;
    const int ty = tid >> 4;

    const int ar = tid >> 1;
    const int ak = (tid & 1) * 4;
    const float* aptr = X + (size_t)(by * 128 + ar) * D_ + ak;
    const int bk = tid >> 5;
    const int bc = (tid & 31) * 4;
    const float* bptr = Wx + (size_t)bk * G_ + bx * 128 + bc;

    ull acc[8][4];
    #pragma unroll
    for (int i = 0; i < 8; i++)
        #pragma unroll
        for (int j = 0; j < 4; j++) acc[i][j] = 0ULL;

    float4 ra = *(const float4*)(aptr);
    float4 rb = *(const float4*)(bptr);
    As[0][ak + 0][ar] = ra.x; As[0][ak + 1][ar] = ra.y;
    As[0][ak + 2][ar] = ra.z; As[0][ak + 3][ar] = ra.w;
    *(float4*)&Bs[0][bk][bc] = rb;
    __syncthreads();

    int buf = 0;
    const int NT = D_ / 8;
    for (int kt = 0; kt < NT; kt++) {
        if (kt + 1 < NT) {
            ra = *(const float4*)(aptr + (kt + 1) * 8);
            rb = *(const float4*)(bptr + (size_t)(kt + 1) * 8 * G_);
        }
        #pragma unroll
        for (int k = 0; k < 8; k++) {
            float4 a0 = *(const float4*)&As[buf][k][ty * 8];
            float4 a1 = *(const float4*)&As[buf][k][ty * 8 + 4];
            float4 b0 = *(const float4*)&Bs[buf][k][tx * 8];
            float4 b1 = *(const float4*)&Bs[buf][k][tx * 8 + 4];
            ull bp0 = pack2(b0.x, b0.y);
            ull bp1 = pack2(b0.z, b0.w);
            ull bp2 = pack2(b1.x, b1.y);
            ull bp3 = pack2(b1.z, b1.w);
            float av[8] = {a0.x, a0.y, a0.z, a0.w, a1.x, a1.y, a1.z, a1.w};
            #pragma unroll
            for (int i = 0; i < 8; i++) {
                ull ap = pack2(av[i], av[i]);
                ffma2(acc[i][0], ap, bp0);
                ffma2(acc[i][1], ap, bp1);
                ffma2(acc[i][2], ap, bp2);
                ffma2(acc[i][3], ap, bp3);
            }
        }
        if (kt + 1 < NT) {
            int nb = buf ^ 1;
            As[nb][ak + 0][ar] = ra.x; As[nb][ak + 1][ar] = ra.y;
            As[nb][ak + 2][ar] = ra.z; As[nb][ak + 3][ar] = ra.w;
            *(float4*)&Bs[nb][bk][bc] = rb;
            __syncthreads();
            buf = nb;
        }
    }

    const int colbase = bx * 128 + tx * 8;
    float4 bb0 = *(const float4*)(bias + colbase);
    float4 bb1 = *(const float4*)(bias + colbase + 4);
    #pragma unroll
    for (int i = 0; i < 8; i++) {
        int row = by * 128 + ty * 8 + i;
        float x0, x1, x2, x3, x4, x5, x6, x7;
        unpack2(acc[i][0], x0, x1); unpack2(acc[i][1], x2, x3);
        unpack2(acc[i][2], x4, x5); unpack2(acc[i][3], x6, x7);
        float4 o0 = {x0 + bb0.x, x1 + bb0.y, x2 + bb0.z, x3 + bb0.w};
        float4 o1 = {x4 + bb1.x, x5 + bb1.y, x6 + bb1.z, x7 + bb1.w};
        float* cp = g_xw + (size_t)row * G_ + colbase;
        *(float4*)cp = o0;
        *(float4*)(cp + 4) = o1;
    }
}

// ---------------- Phase B SMEM ----------------
// Whs: 64 rows (hi 0-31 | lo 32-63) x 1024 fp16, pitch 2064 B -> 132096 B
// sm_p: [4 ksplit][32 m][66 n] f32 -> 33792 B
#define WHS_PITCH 2064
#define SMP_OFF   132096
#define SMEM_TOT  (132096 + 33792)   // 165888

__global__ __launch_bounds__(512, 1)
void lstm_mma(float* __restrict__ out) {
    extern __shared__ char smem[];
    const uint32_t sb = smem_u32(smem);
    float* sm_p = (float*)(smem + SMP_OFF);   // [4][32][66]

    const int tid  = threadIdx.x;
    const int wid  = tid >> 5;
    const int lane = tid & 31;
    const int b    = blockIdx.x;

    // ---- one-time: Wh slice -> padded SMEM (8192 x 16B) ----
    {
        const char* src = (const char*)(g_whs + (size_t)b * 2 * 32 * 1024);
        for (int p = tid; p < 8192; p += 512) {
            int row = p >> 7;
            int seg = p & 127;
            cp16(sb + row * WHS_PITCH + seg * 16, src + row * 2048 + seg * 16);
        }
        cp_commit();
        cp_wait0();
        __syncthreads();
    }

    // warp tiling: wk (k 4-split) x wm (m16 half) x wn (n32 half)
    const int wk = wid & 3;
    const int wm = (wid >> 2) & 1;
    const int wn = wid >> 3;
    const int kk0 = wk * 16;

    // A ldmatrix lane address (hi rows 0-31, lo rows 32-63)
    const uint32_t aHiBase = sb + (uint32_t)(wm * 16 + (lane & 15)) * WHS_PITCH
                                + (uint32_t)(lane >> 4) * 16;
    const uint32_t aLoBase = aHiBase + 32 * WHS_PITCH;

    // partial-store mapping
    const int prow = lane >> 2;
    const int pcol = (lane & 3) * 2;
    float* pbase  = sm_p + ((wk * 32) + wm * 16 + prow) * 66 + wn * 32 + pcol;

    // epilogue mapping: one (n, j) per thread
    const int en = tid >> 3;
    const int ej = tid & 7;
    const int jg = b * 8 + ej;
    float cc = 0.0f;
    // h fragment writer address
    const int wlane = (en & 7) * 4 + ((jg & 7) >> 1);
    const int widx8 = ((en >> 3) & 1) * 4 + (((jg >> 3) & 1) * 2 + (jg & 1));
    __half* hwp = &g_hf[0][jg >> 4][en >> 4][wlane][widx8];
    const size_t hphase_stride = (size_t)64 * 4 * 32 * 8;   // halfs per phase

    for (int t = 0; t < T_; t++) {
        const int p = t & 1, q = p ^ 1;
        // uint4 fragment pairs: index (k16*4 + np)*32 + lane
        const uint4* bPtr = (const uint4*)&g_hf[p][0][0][0][0] + lane;
        const int np0 = wn * 2;

        float d[4][4], dl[4][4];
        #pragma unroll
        for (int j = 0; j < 4; j++)
            #pragma unroll
            for (int i = 0; i < 4; i++) { d[j][i] = 0.0f; dl[j][i] = 0.0f; }

        uint4 bA0, bA1, bB0, bB1;
        uint32_t aA[8], aB[8];

        // preload s=0 (B first: it's the post-barrier critical path)
        bA0 = bPtr[(kk0 * 4 + np0) * 32];
        bA1 = bPtr[(kk0 * 4 + np0 + 1) * 32];
        ldm4(aHiBase + kk0 * 32, aA);
        ldm4(aLoBase + kk0 * 32, aA + 4);

        // prefetch xW pre-activations (independent; consumed in epilogue)
        float xw[4];
        {
            const float* xp = g_xw + ((size_t)en * T_ + t) * G_ + jg;
            #pragma unroll
            for (int g = 0; g < 4; g++) xw[g] = xp[g * 1024];
        }

        #pragma unroll
        for (int s = 0; s < 16; s += 2) {
            // prefetch s+1
            {
                int kk = kk0 + s + 1;
                bB0 = bPtr[(kk * 4 + np0) * 32];
                bB1 = bPtr[(kk * 4 + np0 + 1) * 32];
                ldm4(aHiBase + kk * 32, aB);
                ldm4(aLoBase + kk * 32, aB + 4);
            }
            // compute s
            mma16816(d[0],  aA,     bA0.x, bA0.y);
            mma16816(d[1],  aA,     bA0.z, bA0.w);
            mma16816(d[2],  aA,     bA1.x, bA1.y);
            mma16816(d[3],  aA,     bA1.z, bA1.w);
            mma16816(dl[0], aA + 4, bA0.x, bA0.y);
            mma16816(dl[1], aA + 4, bA0.z, bA0.w);
            mma16816(dl[2], aA + 4, bA1.x, bA1.y);
            mma16816(dl[3], aA + 4, bA1.z, bA1.w);
            // prefetch s+2
            if (s + 2 < 16) {
                int kk = kk0 + s + 2;
                bA0 = bPtr[(kk * 4 + np0) * 32];
                bA1 = bPtr[(kk * 4 + np0 + 1) * 32];
                ldm4(aHiBase + kk * 32, aA);
                ldm4(aLoBase + kk * 32, aA + 4);
            }
            // compute s+1
            mma16816(d[0],  aB,     bB0.x, bB0.y);
            mma16816(d[1],  aB,     bB0.z, bB0.w);
            mma16816(d[2],  aB,     bB1.x, bB1.y);
            mma16816(d[3],  aB,     bB1.z, bB1.w);
            mma16816(dl[0], aB + 4, bB0.x, bB0.y);
            mma16816(dl[1], aB + 4, bB0.z, bB0.w);
            mma16816(dl[2], aB + 4, bB1.x, bB1.y);
            mma16816(dl[3], aB + 4, bB1.z, bB1.w);
        }

        // ---- combine hi + lo/2048, store partials ----
        #pragma unroll
        for (int j = 0; j < 4; j++) {
            float f0 = fmaf(dl[j][0], INV2048, d[j][0]);
            float f1 = fmaf(dl[j][1], INV2048, d[j][1]);
            float f2 = fmaf(dl[j][2], INV2048, d[j][2]);
            float f3 = fmaf(dl[j][3], INV2048, d[j][3]);
            *(float2*)(pbase + j * 8)          = make_float2(f0, f1);
            *(float2*)(pbase + j * 8 + 8 * 66) = make_float2(f2, f3);
        }
        __syncthreads();

        // ---- gates + state update ----
        {
            float a[4];
            #pragma unroll
            for (int g = 0; g < 4; g++) {
                int row = g * 8 + ej;
                float s0 = sm_p[(0 * 32 + row) * 66 + en] + sm_p[(1 * 32 + row) * 66 + en];
                float s1 = sm_p[(2 * 32 + row) * 66 + en] + sm_p[(3 * 32 + row) * 66 + en];
                a[g] = s0 + s1 + xw[g];
            }
            float ig = sigmoidf_(a[0]), fg = sigmoidf_(a[1]), og = sigmoidf_(a[2]);
            float gg = fast_tanh(a[3]);
            cc = fg * cc + ig * gg;
            float h = og * fast_tanh(cc);
            out[((size_t)en * T_ + t) * H_ + jg] = h;
            hwp[(size_t)q * hphase_stride] = __float2half_rn(h);
        }

        // ---- grid barrier (release-arrive; CTA stores ordered by syncthreads) ----
        __syncthreads();
        if (tid == 0) {
            asm volatile("red.release.gpu.global.add.u32 [%0], 1;" :: "l"(&g_count) : "memory");
            unsigned want = (unsigned)(t + 1) * NCTA;
            unsigned v;
            asm volatile("ld.acquire.gpu.global.u32 %0, [%1];" : "=r"(v) : "l"(&g_count) : "memory");
            while (v < want) {
                __nanosleep(32);
                asm volatile("ld.acquire.gpu.global.u32 %0, [%1];" : "=r"(v) : "l"(&g_count) : "memory");
            }
        }
        __syncthreads();
    }
}

// ---------------- launch ----------------
extern "C" void kernel_launch(void* const* d_in, const int* in_sizes, int n_in,
                              void* d_out, int out_size) {
    const float* x  = (const float*)d_in[0];   // (N, T, D)
    const float* h0 = (const float*)d_in[1];   // (N, H)
    const float* Wx = (const float*)d_in[2];   // (D, 4H)
    const float* Wh = (const float*)d_in[3];   // (H, 4H)
    const float* b  = (const float*)d_in[4];   // (4H,)
    float* out = (float*)d_out;                // (N, T, H)

    prep_h0<<<(N_ * H_ + 255) / 256, 256>>>(h0);
    prep_wh<<<NCTA, 256>>>(Wh);

    dim3 gridA(G_ / 128, M_ / 128);
    gemm_xw_kernel<<<gridA, 256>>>(x, Wx, b);

    cudaFuncSetAttribute(lstm_mma, cudaFuncAttributeMaxDynamicSharedMemorySize, SMEM_TOT);
    lstm_mma<<<NCTA, 512, SMEM_TOT>>>(out);
}

// round 9
// speedup vs baseline: 9.3741x; 1.7744x over previous
#include <cuda_runtime.h>
#include <cuda_fp16.h>
#include <cstdint>

// LSTM N=64, T=512, D=1024, H=1024, G=4096.
// Phase A: xW = x @ Wx + b  -- HMMA fp16, Wx 2-term split (hi + lo*2048), x fp16.
// Phase B: persistent kernel, 128 CTAs x 512 threads, HMMA fp16 2-term split on Wh,
//          h single fp16, pre-fragmented h layout, M32xN16 warp tiles.
// R9 fix: phase-A B-fragment register pairing (ldmatrix r0/r2, r1/r3).

#define N_  64
#define T_  512
#define D_  1024
#define H_  1024
#define G_  4096
#define M_  (N_ * T_)
#define NCTA 128
#define INV2048 (1.0f / 2048.0f)

typedef unsigned long long ull;

// -------- device globals --------
static __device__ __align__(16) float  g_xw[(size_t)M_ * G_];          // 512 MB
static __device__ __align__(16) __half g_xh[(size_t)M_ * D_];          // 64 MB  x fp16
static __device__ __align__(16) __half g_wxT[2ULL * G_ * D_];          // 16 MB  Wx^T split [term][col][k]
static __device__ __align__(16) __half g_whs[NCTA * 2 * 32 * 1024];    // 16 MB  split Wh^T
// h fragments: [phase][k16 0..63][np 0..3][lane 0..31][8 fp16]
static __device__ __align__(16) __half g_hf[2][64][4][32][8];
static __device__ unsigned g_count;

__device__ __forceinline__ float sigmoidf_(float x) { return 1.0f / (1.0f + __expf(-x)); }
__device__ __forceinline__ float fast_tanh(float x) {
    float ax = fabsf(x);
    float e = __expf(-2.0f * ax);
    float t = (1.0f - e) / (1.0f + e);
    return copysignf(t, x);
}

// -------- async copy --------
__device__ __forceinline__ void cp16(uint32_t s, const void* g) {
    asm volatile("cp.async.cg.shared.global [%0], [%1], 16;" :: "r"(s), "l"(g));
}
__device__ __forceinline__ void cp_commit() { asm volatile("cp.async.commit_group;"); }
template <int NN>
__device__ __forceinline__ void cp_wait() { asm volatile("cp.async.wait_group %0;" :: "n"(NN)); }

__device__ __forceinline__ uint32_t smem_u32(const void* p) {
    uint32_t a;
    asm("{ .reg .u64 t; cvta.to.shared.u64 t, %1; cvt.u32.u64 %0, t; }" : "=r"(a) : "l"(p));
    return a;
}

// -------- mma helpers --------
__device__ __forceinline__ void ldm4(uint32_t addr, uint32_t* r) {
    asm volatile("ldmatrix.sync.aligned.m8n8.x4.shared.b16 {%0,%1,%2,%3}, [%4];"
                 : "=r"(r[0]), "=r"(r[1]), "=r"(r[2]), "=r"(r[3]) : "r"(addr));
}
__device__ __forceinline__ void mma16816(float* d, const uint32_t* a, uint32_t b0, uint32_t b1) {
    asm volatile(
        "mma.sync.aligned.m16n8k16.row.col.f32.f16.f16.f32 "
        "{%0,%1,%2,%3}, {%4,%5,%6,%7}, {%8,%9}, {%0,%1,%2,%3};"
        : "+f"(d[0]), "+f"(d[1]), "+f"(d[2]), "+f"(d[3])
        : "r"(a[0]), "r"(a[1]), "r"(a[2]), "r"(a[3]), "r"(b0), "r"(b1));
}

// ---------------- prep kernels ----------------
__global__ void prep_x(const float* __restrict__ x) {
    size_t i = ((size_t)blockIdx.x * 256 + threadIdx.x) * 4;
    float4 v = *(const float4*)(x + i);
    __half h[4] = {__float2half_rn(v.x), __float2half_rn(v.y),
                   __float2half_rn(v.z), __float2half_rn(v.w)};
    *(uint2*)(g_xh + i) = *(uint2*)h;
}

__global__ void prep_wx(const float* __restrict__ Wx) {
    int k = blockIdx.x;                     // 0..1023
    const float* src = Wx + (size_t)k * G_;
    for (int col = threadIdx.x; col < G_; col += 256) {
        float w = src[col];
        __half hi = __float2half_rn(w);
        __half lo = __float2half_rn((w - __half2float(hi)) * 2048.0f);
        g_wxT[(size_t)col * D_ + k]        = hi;
        g_wxT[(size_t)(G_ + col) * D_ + k] = lo;
    }
}

__global__ void prep_wh(const float* __restrict__ Wh) {
    int b = blockIdx.x;
    int tid = threadIdx.x;
    int m = tid & 31;
    int g = m >> 3, j = m & 7;
    int col = g * 1024 + b * 8 + j;
    __half* dh = g_whs + ((size_t)(b * 2 + 0) * 32 + m) * 1024;
    __half* dl = g_whs + ((size_t)(b * 2 + 1) * 32 + m) * 1024;
    for (int k = tid >> 5; k < 1024; k += 8) {
        float w = Wh[(size_t)k * G_ + col];
        __half hi = __float2half_rn(w);
        __half lo = __float2half_rn((w - __half2float(hi)) * 2048.0f);
        dh[k] = hi;
        dl[k] = lo;
    }
}

__global__ void prep_h0(const float* __restrict__ h0) {
    int i = blockIdx.x * blockDim.x + threadIdx.x;
    if (i < N_ * H_) {
        int n = i >> 10, k = i & 1023;
        int lane = (n & 7) * 4 + ((k & 7) >> 1);
        int idx8 = ((n >> 3) & 1) * 4 + (((k >> 3) & 1) * 2 + (k & 1));
        g_hf[0][k >> 4][n >> 4][lane][idx8] = __float2half_rn(h0[i]);
    }
    if (i == 0) g_count = 0u;
}

// ---------------- Phase A: xW = x @ Wx + b via HMMA ----------------
// CTA tile M=128 x N=64, K streamed in k64 chunks (16 iters), double-buffered.
// 8 warps: wm 0..3 (m32), wn 0..1 (n32). Wx 2-term (B operand), x single fp16 (A).
#define PA_PITCH 144                      // 64 halfs + 8 pad, bytes
#define PA_ABUF(i) ((i) * 18432)
#define PA_BBUF(i) (36864 + (i) * 18432)
#define PA_SMEM 73728

__global__ __launch_bounds__(256, 2)
void gemm_xw_hmma(const float* __restrict__ bias) {
    extern __shared__ char smem[];
    const uint32_t sb = smem_u32(smem);

    const int tid  = threadIdx.x;
    const int wid  = tid >> 5;
    const int lane = tid & 31;
    const int bx = blockIdx.x;            // n-tile (64 cols)
    const int by = blockIdx.y;            // m-tile (128 rows)
    const int m0 = by * 128;
    const int n0 = bx * 64;

    const char* Asrc = (const char*)g_xh + (size_t)m0 * 2048;    // + row*2048 + k*2
    const char* Bsrc = (const char*)g_wxT;                        // [term*4096 + col][k]

    const int wm = wid >> 1;
    const int wn = wid & 1;

    auto issue = [&](int kt, int bi) {
        const int k0b = kt * 128;
        const uint32_t ab = sb + PA_ABUF(bi);
        const uint32_t bb = sb + PA_BBUF(bi);
        #pragma unroll
        for (int i = 0; i < 4; i++) {
            int p = tid + 256 * i;
            int row = p >> 3, seg = p & 7;
            cp16(ab + row * PA_PITCH + seg * 16,
                 Asrc + (size_t)row * 2048 + k0b + seg * 16);
        }
        #pragma unroll
        for (int i = 0; i < 4; i++) {
            int p = tid + 256 * i;
            int row = p >> 3, seg = p & 7;
            int term = row >> 6, n = row & 63;
            cp16(bb + row * PA_PITCH + seg * 16,
                 Bsrc + ((size_t)term * G_ + n0 + n) * 2048 + k0b + seg * 16);
        }
    };

    float acc[2][2][4][4];                 // [term][mi][n8][4]
    #pragma unroll
    for (int s = 0; s < 2; s++)
        #pragma unroll
        for (int mi = 0; mi < 2; mi++)
            #pragma unroll
            for (int j = 0; j < 4; j++)
                #pragma unroll
                for (int i = 0; i < 4; i++) acc[s][mi][j][i] = 0.0f;

    const uint32_t lrow = (uint32_t)(lane & 15);
    const uint32_t lseg = (uint32_t)(lane >> 4) * 16;

    issue(0, 0);
    cp_commit();

    for (int kt = 0; kt < 16; kt++) {
        if (kt < 15) { issue(kt + 1, (kt + 1) & 1); cp_commit(); cp_wait<1>(); }
        else         { cp_wait<0>(); }
        __syncthreads();

        const uint32_t ab = sb + PA_ABUF(kt & 1);
        const uint32_t bb = sb + PA_BBUF(kt & 1);
        const uint32_t aA0 = ab + (wm * 32 + lrow) * PA_PITCH + lseg;
        const uint32_t aA1 = aA0 + 16 * PA_PITCH;

        #pragma unroll
        for (int k16 = 0; k16 < 4; k16++) {
            uint32_t af[2][4];
            ldm4(aA0 + k16 * 32, af[0]);
            ldm4(aA1 + k16 * 32, af[1]);
            #pragma unroll
            for (int s = 0; s < 2; s++) {
                #pragma unroll
                for (int tau = 0; tau < 2; tau++) {
                    uint32_t bf[4];
                    uint32_t baddr = bb + (s * 64 + wn * 32 + tau * 16 + lrow) * PA_PITCH
                                        + lseg + k16 * 32;
                    ldm4(baddr, bf);
                    // ldmatrix x4 on [n][k]: r0=n0-7/k0-7, r1=n8-15/k0-7,
                    // r2=n0-7/k8-15, r3=n8-15/k8-15  ->  pairs (r0,r2), (r1,r3)
                    mma16816(acc[s][0][tau * 2 + 0], af[0], bf[0], bf[2]);
                    mma16816(acc[s][0][tau * 2 + 1], af[0], bf[1], bf[3]);
                    mma16816(acc[s][1][tau * 2 + 0], af[1], bf[0], bf[2]);
                    mma16816(acc[s][1][tau * 2 + 1], af[1], bf[1], bf[3]);
                }
            }
        }
        __syncthreads();
    }

    // epilogue: combine hi + lo/2048 + bias, write f32
    const int erow = lane >> 2;
    const int ecol = (lane & 3) * 2;
    #pragma unroll
    for (int mi = 0; mi < 2; mi++) {
        #pragma unroll
        for (int j = 0; j < 4; j++) {
            int col = n0 + wn * 32 + j * 8 + ecol;
            float2 bb2 = *(const float2*)(bias + col);
            int row = m0 + wm * 32 + mi * 16 + erow;
            float c0 = fmaf(acc[1][mi][j][0], INV2048, acc[0][mi][j][0]) + bb2.x;
            float c1 = fmaf(acc[1][mi][j][1], INV2048, acc[0][mi][j][1]) + bb2.y;
            float c2 = fmaf(acc[1][mi][j][2], INV2048, acc[0][mi][j][2]) + bb2.x;
            float c3 = fmaf(acc[1][mi][j][3], INV2048, acc[0][mi][j][3]) + bb2.y;
            *(float2*)(g_xw + (size_t)row * G_ + col)       = make_float2(c0, c1);
            *(float2*)(g_xw + (size_t)(row + 8) * G_ + col) = make_float2(c2, c3);
        }
    }
}

// ---------------- Phase B SMEM ----------------
#define WHS_PITCH 2064
#define SMP_OFF   132096
#define SMEM_TOT  (132096 + 33792)   // 165888

__global__ __launch_bounds__(512, 1)
void lstm_mma(float* __restrict__ out) {
    extern __shared__ char smem[];
    const uint32_t sb = smem_u32(smem);
    float* sm_p = (float*)(smem + SMP_OFF);   // [4 wk][32 m][66 n]

    const int tid  = threadIdx.x;
    const int wid  = tid >> 5;
    const int lane = tid & 31;
    const int b    = blockIdx.x;

    // ---- one-time: Wh slice -> padded SMEM ----
    {
        const char* src = (const char*)(g_whs + (size_t)b * 2 * 32 * 1024);
        for (int p = tid; p < 8192; p += 512) {
            int row = p >> 7;
            int seg = p & 127;
            cp16(sb + row * WHS_PITCH + seg * 16, src + row * 2048 + seg * 16);
        }
        cp_commit();
        cp_wait<0>();
        __syncthreads();
    }

    // warp tiling: wk (k 4-split) x wn (n16 quarter); each warp does all 32 m rows
    const int wk = wid & 3;
    const int wn = wid >> 2;          // 0..3
    const int kk0 = wk * 16;

    const uint32_t aBase = sb + (uint32_t)(lane & 15) * WHS_PITCH + (uint32_t)(lane >> 4) * 16;
    const uint32_t aHi0 = aBase;
    const uint32_t aHi1 = aBase + 16 * WHS_PITCH;
    const uint32_t aLo0 = aBase + 32 * WHS_PITCH;
    const uint32_t aLo1 = aBase + 48 * WHS_PITCH;

    const int prow = lane >> 2;
    const int pcol = (lane & 3) * 2;

    const int en = tid >> 3;
    const int ej = tid & 7;
    const int jg = b * 8 + ej;
    float cc = 0.0f;
    const int wlane = (en & 7) * 4 + ((jg & 7) >> 1);
    const int widx8 = ((en >> 3) & 1) * 4 + (((jg >> 3) & 1) * 2 + (jg & 1));
    __half* hwp = &g_hf[0][jg >> 4][en >> 4][wlane][widx8];
    const size_t hphase_stride = (size_t)64 * 4 * 32 * 8;

    for (int t = 0; t < T_; t++) {
        const int p = t & 1, q = p ^ 1;
        const uint4* bPtr = (const uint4*)&g_hf[p][0][0][0][0] + lane;

        float dh[2][2][4], dl[2][2][4];
        #pragma unroll
        for (int m = 0; m < 2; m++)
            #pragma unroll
            for (int j = 0; j < 2; j++)
                #pragma unroll
                for (int i = 0; i < 4; i++) { dh[m][j][i] = 0.0f; dl[m][j][i] = 0.0f; }

        uint4 bA, bB;
        uint32_t aA[16], aB[16];

        bA = bPtr[(kk0 * 4 + wn) * 32];
        ldm4(aHi0 + kk0 * 32, aA);
        ldm4(aHi1 + kk0 * 32, aA + 4);
        ldm4(aLo0 + kk0 * 32, aA + 8);
        ldm4(aLo1 + kk0 * 32, aA + 12);

        float xw[4];
        {
            const float* xp = g_xw + ((size_t)en * T_ + t) * G_ + jg;
            #pragma unroll
            for (int g = 0; g < 4; g++) xw[g] = xp[g * 1024];
        }

        #pragma unroll
        for (int s = 0; s < 16; s += 2) {
            {
                int kk = kk0 + s + 1;
                bB = bPtr[(kk * 4 + wn) * 32];
                ldm4(aHi0 + kk * 32, aB);
                ldm4(aHi1 + kk * 32, aB + 4);
                ldm4(aLo0 + kk * 32, aB + 8);
                ldm4(aLo1 + kk * 32, aB + 12);
            }
            mma16816(dh[0][0], aA,      bA.x, bA.y);
            mma16816(dh[0][1], aA,      bA.z, bA.w);
            mma16816(dh[1][0], aA + 4,  bA.x, bA.y);
            mma16816(dh[1][1], aA + 4,  bA.z, bA.w);
            mma16816(dl[0][0], aA + 8,  bA.x, bA.y);
            mma16816(dl[0][1], aA + 8,  bA.z, bA.w);
            mma16816(dl[1][0], aA + 12, bA.x, bA.y);
            mma16816(dl[1][1], aA + 12, bA.z, bA.w);
            if (s + 2 < 16) {
                int kk = kk0 + s + 2;
                bA = bPtr[(kk * 4 + wn) * 32];
                ldm4(aHi0 + kk * 32, aA);
                ldm4(aHi1 + kk * 32, aA + 4);
                ldm4(aLo0 + kk * 32, aA + 8);
                ldm4(aLo1 + kk * 32, aA + 12);
            }
            mma16816(dh[0][0], aB,      bB.x, bB.y);
            mma16816(dh[0][1], aB,      bB.z, bB.w);
            mma16816(dh[1][0], aB + 4,  bB.x, bB.y);
            mma16816(dh[1][1], aB + 4,  bB.z, bB.w);
            mma16816(dl[0][0], aB + 8,  bB.x, bB.y);
            mma16816(dl[0][1], aB + 8,  bB.z, bB.w);
            mma16816(dl[1][0], aB + 12, bB.x, bB.y);
            mma16816(dl[1][1], aB + 12, bB.z, bB.w);
        }

        // ---- combine + store partials ----
        #pragma unroll
        for (int m = 0; m < 2; m++) {
            #pragma unroll
            for (int j = 0; j < 2; j++) {
                float f0 = fmaf(dl[m][j][0], INV2048, dh[m][j][0]);
                float f1 = fmaf(dl[m][j][1], INV2048, dh[m][j][1]);
                float f2 = fmaf(dl[m][j][2], INV2048, dh[m][j][2]);
                float f3 = fmaf(dl[m][j][3], INV2048, dh[m][j][3]);
                float* qp = sm_p + (wk * 32 + m * 16 + prow) * 66 + wn * 16 + j * 8 + pcol;
                *(float2*)qp            = make_float2(f0, f1);
                *(float2*)(qp + 8 * 66) = make_float2(f2, f3);
            }
        }
        __syncthreads();

        // ---- gates + state update ----
        {
            float a[4];
            #pragma unroll
            for (int g = 0; g < 4; g++) {
                int row = g * 8 + ej;
                float s0 = sm_p[(0 * 32 + row) * 66 + en] + sm_p[(1 * 32 + row) * 66 + en];
                float s1 = sm_p[(2 * 32 + row) * 66 + en] + sm_p[(3 * 32 + row) * 66 + en];
                a[g] = s0 + s1 + xw[g];
            }
            float ig = sigmoidf_(a[0]), fg = sigmoidf_(a[1]), og = sigmoidf_(a[2]);
            float gg = fast_tanh(a[3]);
            cc = fg * cc + ig * gg;
            float h = og * fast_tanh(cc);
            out[((size_t)en * T_ + t) * H_ + jg] = h;
            hwp[(size_t)q * hphase_stride] = __float2half_rn(h);
        }

        // ---- grid barrier ----
        __syncthreads();
        if (tid == 0) {
            asm volatile("red.release.gpu.global.add.u32 [%0], 1;" :: "l"(&g_count) : "memory");
            unsigned want = (unsigned)(t + 1) * NCTA;
            unsigned v;
            asm volatile("ld.acquire.gpu.global.u32 %0, [%1];" : "=r"(v) : "l"(&g_count) : "memory");
            while (v < want) {
                __nanosleep(32);
                asm volatile("ld.acquire.gpu.global.u32 %0, [%1];" : "=r"(v) : "l"(&g_count) : "memory");
            }
        }
        __syncthreads();
    }
}

// ---------------- launch ----------------
extern "C" void kernel_launch(void* const* d_in, const int* in_sizes, int n_in,
                              void* d_out, int out_size) {
    const float* x  = (const float*)d_in[0];   // (N, T, D)
    const float* h0 = (const float*)d_in[1];   // (N, H)
    const float* Wx = (const float*)d_in[2];   // (D, 4H)
    const float* Wh = (const float*)d_in[3];   // (H, 4H)
    const float* b  = (const float*)d_in[4];   // (4H,)
    float* out = (float*)d_out;                // (N, T, H)

    prep_x<<<(int)((size_t)M_ * D_ / 1024), 256>>>(x);
    prep_wx<<<D_, 256>>>(Wx);
    prep_wh<<<NCTA, 256>>>(Wh);
    prep_h0<<<(N_ * H_ + 255) / 256, 256>>>(h0);

    cudaFuncSetAttribute(gemm_xw_hmma, cudaFuncAttributeMaxDynamicSharedMemorySize, PA_SMEM);
    dim3 gridA(G_ / 64, M_ / 128);
    gemm_xw_hmma<<<gridA, 256, PA_SMEM>>>(b);

    cudaFuncSetAttribute(lstm_mma, cudaFuncAttributeMaxDynamicSharedMemorySize, SMEM_TOT);
    lstm_mma<<<NCTA, 512, SMEM_TOT>>>(out);
}